// round 1
// baseline (speedup 1.0000x reference)
#include <cuda_runtime.h>
#include <math.h>

#define TT     4096      // total tokens B*S
#define HIDDIM 3584
#define NH     16
#define NKV    8
#define HD     256
#define SEQ    2048
#define NB     2
#define QKVW   8192      // (NH + 2*NKV) * HD
#define ATTW   4096      // NH * HD
#define WIN    1024
#define QSCALE 0.0625f   // 256^-0.5
#define SOFTCAP 50.0f

#define BQ 64
#define BK 64

// Scratch (static device allocations; no runtime alloc allowed)
__device__ float g_qkv[(size_t)TT * QKVW];      // 128 MB
__device__ float g_att[(size_t)TT * ATTW];      //  64 MB
__device__ float g_qT[(size_t)NH * HD * TT];    //  64 MB   [h][d][t], RoPE'd + scaled
__device__ float g_kT[(size_t)NKV * HD * TT];   //  32 MB   [kh][d][t], RoPE'd

// ---------------------------------------------------------------------------
// SGEMM NT: C[m,n] = sum_k A[m,k]*B[n,k]. 128x128 tile, BK=8, 256 thr, 8x8/thr
// ---------------------------------------------------------------------------
__global__ __launch_bounds__(256) void sgemm_nt(
    int M, int N, int K,
    const float* __restrict__ A, int lda,
    const float* __restrict__ B, int ldb,
    float* __restrict__ C, int ldc)
{
    __shared__ float As[8][128];
    __shared__ float Bs[8][128];
    const int tid = threadIdx.x;
    const int bm0 = blockIdx.y << 7;
    const int bn0 = blockIdx.x << 7;
    const int lr = tid >> 1;           // 0..127
    const int lk = (tid & 1) << 2;     // 0 or 4
    const float* Ap = A + (size_t)(bm0 + lr) * lda + lk;
    const float* Bp = B + (size_t)(bn0 + lr) * ldb + lk;
    const int ty = tid >> 4, tx = tid & 15;

    float acc[8][8];
#pragma unroll
    for (int i = 0; i < 8; i++)
#pragma unroll
        for (int j = 0; j < 8; j++) acc[i][j] = 0.f;

    float4 av = *(const float4*)Ap;
    float4 bv = *(const float4*)Bp;

    for (int kt = 0; kt < K; kt += 8) {
        __syncthreads();
        As[lk + 0][lr] = av.x; As[lk + 1][lr] = av.y;
        As[lk + 2][lr] = av.z; As[lk + 3][lr] = av.w;
        Bs[lk + 0][lr] = bv.x; Bs[lk + 1][lr] = bv.y;
        Bs[lk + 2][lr] = bv.z; Bs[lk + 3][lr] = bv.w;
        __syncthreads();
        if (kt + 8 < K) {
            av = *(const float4*)(Ap + kt + 8);
            bv = *(const float4*)(Bp + kt + 8);
        }
#pragma unroll
        for (int k = 0; k < 8; k++) {
            float a[8], b[8];
            *(float4*)(a)     = *(const float4*)&As[k][ty << 2];
            *(float4*)(a + 4) = *(const float4*)&As[k][64 + (ty << 2)];
            *(float4*)(b)     = *(const float4*)&Bs[k][tx << 2];
            *(float4*)(b + 4) = *(const float4*)&Bs[k][64 + (tx << 2)];
#pragma unroll
            for (int i = 0; i < 8; i++)
#pragma unroll
                for (int j = 0; j < 8; j++)
                    acc[i][j] = fmaf(a[i], b[j], acc[i][j]);
        }
    }

#pragma unroll
    for (int i = 0; i < 8; i++) {
        int m = bm0 + ((i < 4) ? (ty << 2) + i : 64 + (ty << 2) + (i - 4));
        float4 v0 = make_float4(acc[i][0], acc[i][1], acc[i][2], acc[i][3]);
        float4 v1 = make_float4(acc[i][4], acc[i][5], acc[i][6], acc[i][7]);
        *(float4*)&C[(size_t)m * ldc + bn0 + (tx << 2)]      = v0;
        *(float4*)&C[(size_t)m * ldc + bn0 + 64 + (tx << 2)] = v1;
    }
}

// ---------------------------------------------------------------------------
// RoPE + transpose: g_qkv (row-major) -> g_qT/g_kT ([head][d][t], d-major)
// Q additionally pre-scaled by QSCALE.
// ---------------------------------------------------------------------------
__global__ void rope_transpose(const float* __restrict__ cosb,
                               const float* __restrict__ sinb)
{
    int t  = blockIdx.x;        // 0..4095
    int hh = blockIdx.y;        // 0..23 : 0..15 q heads, 16..23 k heads
    int d  = threadIdx.x;       // 0..127
    const float* row = g_qkv + (size_t)t * QKVW + hh * HD;
    float x1 = row[d], x2 = row[d + 128];
    float c = cosb[t * 128 + d], s = sinb[t * 128 + d];
    float o1 = x1 * c - x2 * s;
    float o2 = x2 * c + x1 * s;
    if (hh < NH) {
        o1 *= QSCALE; o2 *= QSCALE;
        g_qT[(size_t)(hh * HD + d) * TT + t]       = o1;
        g_qT[(size_t)(hh * HD + d + 128) * TT + t] = o2;
    } else {
        int kh = hh - NH;
        g_kT[(size_t)(kh * HD + d) * TT + t]       = o1;
        g_kT[(size_t)(kh * HD + d + 128) * TT + t] = o2;
    }
}

// ---------------------------------------------------------------------------
// Flash attention, fp32, Bq=Bk=64, online softmax, softcap+sliding window.
// smem: Qs[256][64] (d-major), Ks[256][64] (d-major), Vs[64][256], St[64][68]
// ---------------------------------------------------------------------------
#define ST_LD 68
#define ATT_SMEM_FLOATS (16384*3 + 64*ST_LD + 192)
#define ATT_SMEM_BYTES  (ATT_SMEM_FLOATS * 4)

__global__ __launch_bounds__(256) void attn_kernel(float* __restrict__ outp)
{
    extern __shared__ float smf[];
    float* Qs   = smf;               // [256][64]
    float* Ks   = smf + 16384;       // [256][64]
    float* Vs   = smf + 32768;       // [64][256]
    float* St   = smf + 49152;       // [64][ST_LD]  scores/probs, [kc][qr]
    float* rowm = St + 64 * ST_LD;
    float* rowl = rowm + 64;
    float* alf  = rowl + 64;

    const int tid  = threadIdx.x;
    const int qt   = blockIdx.x, h = blockIdx.y, b = blockIdx.z;
    const int qi0  = qt * BQ;
    const int tok0 = b * SEQ;
    const int kh   = h >> 1;           // GQA: 2 q heads per kv head

    // Load Q tile (d-major, already RoPE'd + scaled)
    const float* qsrc = g_qT + (size_t)h * HD * TT + tok0 + qi0;
#pragma unroll
    for (int it = 0; it < 16; it++) {
        int idx = tid + it * 256;
        int d = idx >> 4, c4 = idx & 15;
        *(float4*)&Qs[d * 64 + c4 * 4] =
            *(const float4*)(qsrc + (size_t)d * TT + c4 * 4);
    }
    if (tid < 64) { rowm[tid] = -1e30f; rowl[tid] = 0.f; }

    const int otq = tid >> 4;   // q-row group for O (4 rows)
    const int otd = tid & 15;   // d-chunk for O
    float4 o[4][4];
#pragma unroll
    for (int i = 0; i < 4; i++)
#pragma unroll
        for (int c = 0; c < 4; c++) o[i][c] = make_float4(0.f, 0.f, 0.f, 0.f);
    __syncthreads();

    const int kt0 = (qi0 - WIN > 0) ? (qi0 - WIN) : 0;
    for (int kj0 = kt0; kj0 <= qi0; kj0 += BK) {
        // ---- load K (d-major) and V (row-major) tiles ----
        const float* ksrc = g_kT + (size_t)kh * HD * TT + tok0 + kj0;
#pragma unroll
        for (int it = 0; it < 16; it++) {
            int idx = tid + it * 256;
            int d = idx >> 4, c4 = idx & 15;
            *(float4*)&Ks[d * 64 + c4 * 4] =
                *(const float4*)(ksrc + (size_t)d * TT + c4 * 4);
        }
        const float* vsrc = g_qkv + (size_t)(tok0 + kj0) * QKVW
                          + (NH + NKV) * HD + kh * HD;
#pragma unroll
        for (int it = 0; it < 16; it++) {
            int idx = tid + it * 256;
            int kr = idx >> 6, d4 = idx & 63;
            *(float4*)&Vs[kr * 256 + d4 * 4] =
                *(const float4*)(vsrc + (size_t)kr * QKVW + d4 * 4);
        }
        __syncthreads();

        // ---- Phase A: S = Q K^T (4x4 per thread), softcap + mask ----
        {
            const int tq = tid & 15, tk = tid >> 4;
            float s4[4][4];
#pragma unroll
            for (int i = 0; i < 4; i++)
#pragma unroll
                for (int j = 0; j < 4; j++) s4[i][j] = 0.f;
            for (int d = 0; d < HD; d++) {
                float a[4], bb[4];
                *(float4*)a  = *(const float4*)&Qs[d * 64 + tq * 4];
                *(float4*)bb = *(const float4*)&Ks[d * 64 + tk * 4];
#pragma unroll
                for (int i = 0; i < 4; i++)
#pragma unroll
                    for (int j = 0; j < 4; j++)
                        s4[i][j] = fmaf(a[i], bb[j], s4[i][j]);
            }
#pragma unroll
            for (int i = 0; i < 4; i++) {
#pragma unroll
                for (int j = 0; j < 4; j++) {
                    float sv = SOFTCAP * tanhf(s4[i][j] * (1.0f / SOFTCAP));
                    int ig = qi0 + tq * 4 + i;
                    int jg = kj0 + tk * 4 + j;
                    if (jg > ig || jg < ig - WIN) sv = -1e30f;
                    St[(tk * 4 + j) * ST_LD + tq * 4 + i] = sv;
                }
            }
        }
        __syncthreads();

        // ---- Phase B: online softmax stats (4 threads per row) ----
        {
            int qr = tid >> 2, sub = tid & 3;
            float mx = -1e30f;
#pragma unroll
            for (int ii = 0; ii < 16; ii++)
                mx = fmaxf(mx, St[(sub * 16 + ii) * ST_LD + qr]);
            mx = fmaxf(mx, __shfl_xor_sync(0xffffffffu, mx, 1));
            mx = fmaxf(mx, __shfl_xor_sync(0xffffffffu, mx, 2));
            float mold = rowm[qr];
            float mnew = fmaxf(mold, mx);
            float al   = __expf(mold - mnew);
            float ps   = 0.f;
#pragma unroll
            for (int ii = 0; ii < 16; ii++) {
                int a = (sub * 16 + ii) * ST_LD + qr;
                float sv = St[a];
                float p  = (sv > -1e29f) ? __expf(sv - mnew) : 0.f;
                St[a] = p;
                ps += p;
            }
            ps += __shfl_xor_sync(0xffffffffu, ps, 1);
            ps += __shfl_xor_sync(0xffffffffu, ps, 2);
            if (sub == 0) {
                rowm[qr] = mnew;
                rowl[qr] = rowl[qr] * al + ps;
                alf[qr]  = al;
            }
        }
        __syncthreads();

        // ---- Phase C: O = diag(alpha) O + P V ----
        {
            float ar[4];
#pragma unroll
            for (int i = 0; i < 4; i++) ar[i] = alf[otq * 4 + i];
#pragma unroll
            for (int i = 0; i < 4; i++)
#pragma unroll
                for (int c = 0; c < 4; c++) {
                    o[i][c].x *= ar[i]; o[i][c].y *= ar[i];
                    o[i][c].z *= ar[i]; o[i][c].w *= ar[i];
                }
            for (int kc = 0; kc < BK; kc++) {
                float4 p4 = *(const float4*)&St[kc * ST_LD + otq * 4];
                float pr[4] = { p4.x, p4.y, p4.z, p4.w };
                float4 vv[4];
#pragma unroll
                for (int c = 0; c < 4; c++)
                    vv[c] = *(const float4*)&Vs[kc * 256 + (otd + 16 * c) * 4];
#pragma unroll
                for (int i = 0; i < 4; i++)
#pragma unroll
                    for (int c = 0; c < 4; c++) {
                        o[i][c].x = fmaf(pr[i], vv[c].x, o[i][c].x);
                        o[i][c].y = fmaf(pr[i], vv[c].y, o[i][c].y);
                        o[i][c].z = fmaf(pr[i], vv[c].z, o[i][c].z);
                        o[i][c].w = fmaf(pr[i], vv[c].w, o[i][c].w);
                    }
            }
        }
        __syncthreads();
    }

    // ---- epilogue: normalize and write ----
    float inv[4];
#pragma unroll
    for (int i = 0; i < 4; i++) inv[i] = 1.0f / rowl[otq * 4 + i];
#pragma unroll
    for (int i = 0; i < 4; i++) {
        int token = tok0 + qi0 + otq * 4 + i;
#pragma unroll
        for (int c = 0; c < 4; c++) {
            float4 r;
            r.x = o[i][c].x * inv[i]; r.y = o[i][c].y * inv[i];
            r.z = o[i][c].z * inv[i]; r.w = o[i][c].w * inv[i];
            *(float4*)&outp[(size_t)token * ATTW + h * HD + (otd + 16 * c) * 4] = r;
        }
    }
}

// ---------------------------------------------------------------------------
extern "C" void kernel_launch(void* const* d_in, const int* in_sizes, int n_in,
                              void* d_out, int out_size)
{
    const float* hidden = (const float*)d_in[0];
    const float* cosb   = (const float*)d_in[1];
    const float* sinb   = (const float*)d_in[2];
    const float* w_qkv  = (const float*)d_in[3];
    const float* w_o    = (const float*)d_in[4];
    float* out = (float*)d_out;

    float *d_qkv, *d_att;
    cudaGetSymbolAddress((void**)&d_qkv, g_qkv);
    cudaGetSymbolAddress((void**)&d_att, g_att);

    // 1. QKV projection: (4096 x 3584) x (8192 x 3584)^T
    sgemm_nt<<<dim3(QKVW / 128, TT / 128), 256>>>(
        TT, QKVW, HIDDIM, hidden, HIDDIM, w_qkv, HIDDIM, d_qkv, QKVW);

    // 2. RoPE + transpose into d-major Q/K buffers
    rope_transpose<<<dim3(TT, NH + NKV), 128>>>(cosb, sinb);

    // 3. Sliding-window attention
    cudaFuncSetAttribute(attn_kernel,
                         cudaFuncAttributeMaxDynamicSharedMemorySize,
                         ATT_SMEM_BYTES);
    attn_kernel<<<dim3(SEQ / BQ, NH, NB), 256, ATT_SMEM_BYTES>>>(d_att);

    // 4. Output projection: (4096 x 4096) x (3584 x 4096)^T
    sgemm_nt<<<dim3(HIDDIM / 128, TT / 128), 256>>>(
        TT, HIDDIM, ATTW, d_att, ATTW, w_o, ATTW, out, HIDDIM);
}

// round 8
// speedup vs baseline: 1.5842x; 1.5842x over previous
#include <cuda_runtime.h>
#include <cuda_bf16.h>
#include <math.h>
#include <stdint.h>

#define TT     4096      // total tokens B*S
#define HIDDIM 3584
#define NH     16
#define NKV    8
#define HD     256
#define SEQ    2048
#define NB     2
#define QKVW   8192      // (NH + 2*NKV) * HD
#define ATTW   4096      // NH * HD
#define WIN    1024
#define QSCALE 0.0625f   // 256^-0.5
#define SOFTCAP 50.0f

#define BQ 64
#define BK 64

// ---------------- scratch (static device allocations) ----------------------
__device__ float g_qkv[(size_t)TT * QKVW];      // 128 MB fp32 qkv
__device__ float g_att[(size_t)TT * ATTW];      //  64 MB attention output
__device__ float g_qT[(size_t)NH * HD * TT];    //  [h][d][t] RoPE'd + scaled
__device__ float g_kT[(size_t)NKV * HD * TT];   //  [kh][d][t] RoPE'd

// bf16 split planes (hi + lo) for tensor-core GEMMs
__device__ __nv_bfloat16 g_hidH[(size_t)TT * HIDDIM];
__device__ __nv_bfloat16 g_hidL[(size_t)TT * HIDDIM];
__device__ __nv_bfloat16 g_wqH[(size_t)QKVW * HIDDIM];
__device__ __nv_bfloat16 g_wqL[(size_t)QKVW * HIDDIM];
__device__ __nv_bfloat16 g_aH[(size_t)TT * ATTW];
__device__ __nv_bfloat16 g_aL[(size_t)TT * ATTW];
__device__ __nv_bfloat16 g_woH[(size_t)HIDDIM * ATTW];
__device__ __nv_bfloat16 g_woL[(size_t)HIDDIM * ATTW];

// ---------------------------------------------------------------------------
// fp32 -> bf16 hi/lo split
// ---------------------------------------------------------------------------
__global__ __launch_bounds__(256) void split_bf16(
    const float* __restrict__ src,
    __nv_bfloat16* __restrict__ hi, __nv_bfloat16* __restrict__ lo, size_t n)
{
    size_t i = ((size_t)blockIdx.x * blockDim.x + threadIdx.x) * 4;
    if (i >= n) return;
    float4 v = *(const float4*)(src + i);
    __nv_bfloat16 h0 = __float2bfloat16(v.x);
    __nv_bfloat16 h1 = __float2bfloat16(v.y);
    __nv_bfloat16 h2 = __float2bfloat16(v.z);
    __nv_bfloat16 h3 = __float2bfloat16(v.w);
    __nv_bfloat16 l0 = __float2bfloat16(v.x - __bfloat162float(h0));
    __nv_bfloat16 l1 = __float2bfloat16(v.y - __bfloat162float(h1));
    __nv_bfloat16 l2 = __float2bfloat16(v.z - __bfloat162float(h2));
    __nv_bfloat16 l3 = __float2bfloat16(v.w - __bfloat162float(h3));
    *(__nv_bfloat162*)(hi + i)     = __halves2bfloat162(h0, h1);
    *(__nv_bfloat162*)(hi + i + 2) = __halves2bfloat162(h2, h3);
    *(__nv_bfloat162*)(lo + i)     = __halves2bfloat162(l0, l1);
    *(__nv_bfloat162*)(lo + i + 2) = __halves2bfloat162(l2, l3);
}

// ---------------------------------------------------------------------------
// mma.sync helpers (baseline PTX, compiles for compute_103)
// ---------------------------------------------------------------------------
__device__ __forceinline__ uint32_t smem_u32(const void* p) {
    uint32_t a;
    asm("{ .reg .u64 t; cvta.to.shared.u64 t, %1; cvt.u32.u64 %0, t; }"
        : "=r"(a) : "l"(p));
    return a;
}
__device__ __forceinline__ void ldsm_x4(uint32_t* r, uint32_t addr) {
    asm volatile("ldmatrix.sync.aligned.m8n8.x4.shared.b16 {%0,%1,%2,%3}, [%4];"
                 : "=r"(r[0]), "=r"(r[1]), "=r"(r[2]), "=r"(r[3]) : "r"(addr));
}
__device__ __forceinline__ void ldsm_x2(uint32_t* r, uint32_t addr) {
    asm volatile("ldmatrix.sync.aligned.m8n8.x2.shared.b16 {%0,%1}, [%2];"
                 : "=r"(r[0]), "=r"(r[1]) : "r"(addr));
}
__device__ __forceinline__ void mma_bf16(float* c, const uint32_t* a,
                                         const uint32_t* b) {
    asm volatile(
        "mma.sync.aligned.m16n8k16.row.col.f32.bf16.bf16.f32 "
        "{%0,%1,%2,%3}, {%4,%5,%6,%7}, {%8,%9}, {%0,%1,%2,%3};"
        : "+f"(c[0]), "+f"(c[1]), "+f"(c[2]), "+f"(c[3])
        : "r"(a[0]), "r"(a[1]), "r"(a[2]), "r"(a[3]), "r"(b[0]), "r"(b[1]));
}

// ---------------------------------------------------------------------------
// Tensor-core GEMM (NT): C[m,n] = sum_k A[m,k]*B[n,k], fp32 via bf16 split.
// BM=128, BN=128, BK=32, 8 warps (warp tile 32x64), 4-stage cp.async.
// smem rows padded to 40 bf16 (80B) -> conflict-free ldmatrix.
// ---------------------------------------------------------------------------
#define GBM 128
#define GBN 128
#define GBKT 32
#define ROWB    80                   // padded row bytes (32 bf16 + 8 pad)
#define PLANE_B (128 * ROWB)         // 10240 B : one operand plane
#define STAGE_B (4 * PLANE_B)        // 40960 B : Ah, Al, Bh, Bl
#define NSTAGE  4
#define GEMM_SMEM (NSTAGE * STAGE_B) // 163840 B

__global__ __launch_bounds__(256) void gemm_tc(
    const __nv_bfloat16* __restrict__ Ah, const __nv_bfloat16* __restrict__ Al,
    const __nv_bfloat16* __restrict__ Bh, const __nv_bfloat16* __restrict__ Bl,
    float* __restrict__ C, int M, int N, int K)
{
    extern __shared__ char smg[];
    const uint32_t sb = smem_u32(smg);
    const int tid  = threadIdx.x;
    const int lane = tid & 31;
    const int w    = tid >> 5;
    const int wm   = (w & 3) * 32;    // warp m offset in tile
    const int wn   = (w >> 2) * 64;   // warp n offset in tile
    const int bn0  = blockIdx.x * GBN;
    const int bm0  = blockIdx.y * GBM;
    const int niter = K / GBKT;

    const __nv_bfloat16* srcs[4] = { Ah, Al, Bh, Bl };

    auto load_stage = [&](int kt, int s) {
#pragma unroll
        for (int i = 0; i < 8; i++) {
            int q    = tid + i * 256;      // 0..2047
            int pl   = q >> 9;             // 0:Ah 1:Al 2:Bh 3:Bl
            int r    = q & 511;
            int row  = r >> 2;
            int slot = r & 3;              // 16B slot within 64B row data
            int rb   = (pl < 2) ? bm0 : bn0;
            const __nv_bfloat16* sp = srcs[pl]
                + (size_t)(rb + row) * K + kt * GBKT + slot * 8;
            uint32_t dst = sb + s * STAGE_B + pl * PLANE_B
                         + row * ROWB + slot * 16;
            asm volatile("cp.async.cg.shared.global [%0], [%1], 16;"
                         :: "r"(dst), "l"(sp));
        }
    };

    float acc[2][8][4];
#pragma unroll
    for (int mt = 0; mt < 2; mt++)
#pragma unroll
        for (int nt = 0; nt < 8; nt++)
#pragma unroll
            for (int e = 0; e < 4; e++) acc[mt][nt][e] = 0.f;

    // prologue: fill NSTAGE-1 stages
#pragma unroll
    for (int s = 0; s < NSTAGE - 1; s++) {
        load_stage(s, s);
        asm volatile("cp.async.commit_group;");
    }

    // per-lane fragment address components
    const int a_row = lane & 15, a_half = (lane >> 4) * 8;
    const int b_row = lane & 7,  b_half = ((lane >> 3) & 1) * 8;

    for (int kt = 0; kt < niter; kt++) {
        asm volatile("cp.async.wait_group %0;" :: "n"(NSTAGE - 2));
        __syncthreads();

        if (kt + NSTAGE - 1 < niter)
            load_stage(kt + NSTAGE - 1, (kt + NSTAGE - 1) & (NSTAGE - 1));
        asm volatile("cp.async.commit_group;");

        const uint32_t sbase = sb + (kt & (NSTAGE - 1)) * STAGE_B;
#pragma unroll
        for (int ks = 0; ks < GBKT; ks += 16) {
            uint32_t ah[2][4], al[2][4];
#pragma unroll
            for (int mt = 0; mt < 2; mt++) {
                uint32_t aaddr = sbase + (wm + mt * 16 + a_row) * ROWB
                               + (ks + a_half) * 2;
                ldsm_x4(ah[mt], aaddr);
                ldsm_x4(al[mt], aaddr + PLANE_B);
            }
#pragma unroll
            for (int nt = 0; nt < 8; nt++) {
                uint32_t baddr = sbase + 2 * PLANE_B
                               + (wn + nt * 8 + b_row) * ROWB
                               + (ks + b_half) * 2;
                uint32_t bh[2], bl[2];
                ldsm_x2(bh, baddr);
                ldsm_x2(bl, baddr + PLANE_B);
#pragma unroll
                for (int mt = 0; mt < 2; mt++) {
                    mma_bf16(acc[mt][nt], ah[mt], bh);
                    mma_bf16(acc[mt][nt], ah[mt], bl);
                    mma_bf16(acc[mt][nt], al[mt], bh);
                }
            }
        }
        __syncthreads();
    }

    // epilogue: write fp32 C
    const int cr = lane >> 2, cc = (lane & 3) * 2;
#pragma unroll
    for (int mt = 0; mt < 2; mt++) {
#pragma unroll
        for (int nt = 0; nt < 8; nt++) {
            int row0 = bm0 + wm + mt * 16 + cr;
            int col  = bn0 + wn + nt * 8 + cc;
            *(float2*)&C[(size_t)row0 * N + col] =
                make_float2(acc[mt][nt][0], acc[mt][nt][1]);
            *(float2*)&C[(size_t)(row0 + 8) * N + col] =
                make_float2(acc[mt][nt][2], acc[mt][nt][3]);
        }
    }
}

// ---------------------------------------------------------------------------
// RoPE + transpose: g_qkv (row-major) -> g_qT/g_kT ([head][d][t], d-major)
// ---------------------------------------------------------------------------
__global__ void rope_transpose(const float* __restrict__ cosb,
                               const float* __restrict__ sinb)
{
    int t  = blockIdx.x;
    int hh = blockIdx.y;        // 0..15 q heads, 16..23 k heads
    int d  = threadIdx.x;       // 0..127
    const float* row = g_qkv + (size_t)t * QKVW + hh * HD;
    float x1 = row[d], x2 = row[d + 128];
    float c = cosb[t * 128 + d], s = sinb[t * 128 + d];
    float o1 = x1 * c - x2 * s;
    float o2 = x2 * c + x1 * s;
    if (hh < NH) {
        o1 *= QSCALE; o2 *= QSCALE;
        g_qT[(size_t)(hh * HD + d) * TT + t]       = o1;
        g_qT[(size_t)(hh * HD + d + 128) * TT + t] = o2;
    } else {
        int kh = hh - NH;
        g_kT[(size_t)(kh * HD + d) * TT + t]       = o1;
        g_kT[(size_t)(kh * HD + d + 128) * TT + t] = o2;
    }
}

// ---------------------------------------------------------------------------
// Flash attention, fp32, Bq=Bk=64, online softmax, softcap+sliding window.
// ---------------------------------------------------------------------------
#define ST_LD 68
#define ATT_SMEM_FLOATS (16384*3 + 64*ST_LD + 192)
#define ATT_SMEM_BYTES  (ATT_SMEM_FLOATS * 4)

__global__ __launch_bounds__(256) void attn_kernel(float* __restrict__ outp)
{
    extern __shared__ float smf[];
    float* Qs   = smf;               // [256][64]
    float* Ks   = smf + 16384;       // [256][64]
    float* Vs   = smf + 32768;       // [64][256]
    float* St   = smf + 49152;       // [64][ST_LD]
    float* rowm = St + 64 * ST_LD;
    float* rowl = rowm + 64;
    float* alf  = rowl + 64;

    const int tid  = threadIdx.x;
    const int qt   = blockIdx.x, h = blockIdx.y, b = blockIdx.z;
    const int qi0  = qt * BQ;
    const int tok0 = b * SEQ;
    const int kh   = h >> 1;

    const float* qsrc = g_qT + (size_t)h * HD * TT + tok0 + qi0;
#pragma unroll
    for (int it = 0; it < 16; it++) {
        int idx = tid + it * 256;
        int d = idx >> 4, c4 = idx & 15;
        *(float4*)&Qs[d * 64 + c4 * 4] =
            *(const float4*)(qsrc + (size_t)d * TT + c4 * 4);
    }
    if (tid < 64) { rowm[tid] = -1e30f; rowl[tid] = 0.f; }

    const int otq = tid >> 4;
    const int otd = tid & 15;
    float4 o[4][4];
#pragma unroll
    for (int i = 0; i < 4; i++)
#pragma unroll
        for (int c = 0; c < 4; c++) o[i][c] = make_float4(0.f, 0.f, 0.f, 0.f);
    __syncthreads();

    const int kt0 = (qi0 - WIN > 0) ? (qi0 - WIN) : 0;
    for (int kj0 = kt0; kj0 <= qi0; kj0 += BK) {
        const float* ksrc = g_kT + (size_t)kh * HD * TT + tok0 + kj0;
#pragma unroll
        for (int it = 0; it < 16; it++) {
            int idx = tid + it * 256;
            int d = idx >> 4, c4 = idx & 15;
            *(float4*)&Ks[d * 64 + c4 * 4] =
                *(const float4*)(ksrc + (size_t)d * TT + c4 * 4);
        }
        const float* vsrc = g_qkv + (size_t)(tok0 + kj0) * QKVW
                          + (NH + NKV) * HD + kh * HD;
#pragma unroll
        for (int it = 0; it < 16; it++) {
            int idx = tid + it * 256;
            int kr = idx >> 6, d4 = idx & 63;
            *(float4*)&Vs[kr * 256 + d4 * 4] =
                *(const float4*)(vsrc + (size_t)kr * QKVW + d4 * 4);
        }
        __syncthreads();

        {
            const int tq = tid & 15, tk = tid >> 4;
            float s4[4][4];
#pragma unroll
            for (int i = 0; i < 4; i++)
#pragma unroll
                for (int j = 0; j < 4; j++) s4[i][j] = 0.f;
            for (int d = 0; d < HD; d++) {
                float a[4], bb[4];
                *(float4*)a  = *(const float4*)&Qs[d * 64 + tq * 4];
                *(float4*)bb = *(const float4*)&Ks[d * 64 + tk * 4];
#pragma unroll
                for (int i = 0; i < 4; i++)
#pragma unroll
                    for (int j = 0; j < 4; j++)
                        s4[i][j] = fmaf(a[i], bb[j], s4[i][j]);
            }
#pragma unroll
            for (int i = 0; i < 4; i++) {
#pragma unroll
                for (int j = 0; j < 4; j++) {
                    float sv = SOFTCAP * tanhf(s4[i][j] * (1.0f / SOFTCAP));
                    int ig = qi0 + tq * 4 + i;
                    int jg = kj0 + tk * 4 + j;
                    if (jg > ig || jg < ig - WIN) sv = -1e30f;
                    St[(tk * 4 + j) * ST_LD + tq * 4 + i] = sv;
                }
            }
        }
        __syncthreads();

        {
            int qr = tid >> 2, sub = tid & 3;
            float mx = -1e30f;
#pragma unroll
            for (int ii = 0; ii < 16; ii++)
                mx = fmaxf(mx, St[(sub * 16 + ii) * ST_LD + qr]);
            mx = fmaxf(mx, __shfl_xor_sync(0xffffffffu, mx, 1));
            mx = fmaxf(mx, __shfl_xor_sync(0xffffffffu, mx, 2));
            float mold = rowm[qr];
            float mnew = fmaxf(mold, mx);
            float al   = __expf(mold - mnew);
            float ps   = 0.f;
#pragma unroll
            for (int ii = 0; ii < 16; ii++) {
                int a = (sub * 16 + ii) * ST_LD + qr;
                float sv = St[a];
                float p  = (sv > -1e29f) ? __expf(sv - mnew) : 0.f;
                St[a] = p;
                ps += p;
            }
            ps += __shfl_xor_sync(0xffffffffu, ps, 1);
            ps += __shfl_xor_sync(0xffffffffu, ps, 2);
            if (sub == 0) {
                rowm[qr] = mnew;
                rowl[qr] = rowl[qr] * al + ps;
                alf[qr]  = al;
            }
        }
        __syncthreads();

        {
            float ar[4];
#pragma unroll
            for (int i = 0; i < 4; i++) ar[i] = alf[otq * 4 + i];
#pragma unroll
            for (int i = 0; i < 4; i++)
#pragma unroll
                for (int c = 0; c < 4; c++) {
                    o[i][c].x *= ar[i]; o[i][c].y *= ar[i];
                    o[i][c].z *= ar[i]; o[i][c].w *= ar[i];
                }
            for (int kc = 0; kc < BK; kc++) {
                float4 p4 = *(const float4*)&St[kc * ST_LD + otq * 4];
                float pr[4] = { p4.x, p4.y, p4.z, p4.w };
                float4 vv[4];
#pragma unroll
                for (int c = 0; c < 4; c++)
                    vv[c] = *(const float4*)&Vs[kc * 256 + (otd + 16 * c) * 4];
#pragma unroll
                for (int i = 0; i < 4; i++)
#pragma unroll
                    for (int c = 0; c < 4; c++) {
                        o[i][c].x = fmaf(pr[i], vv[c].x, o[i][c].x);
                        o[i][c].y = fmaf(pr[i], vv[c].y, o[i][c].y);
                        o[i][c].z = fmaf(pr[i], vv[c].z, o[i][c].z);
                        o[i][c].w = fmaf(pr[i], vv[c].w, o[i][c].w);
                    }
            }
        }
        __syncthreads();
    }

    float inv[4];
#pragma unroll
    for (int i = 0; i < 4; i++) inv[i] = 1.0f / rowl[otq * 4 + i];
#pragma unroll
    for (int i = 0; i < 4; i++) {
        int token = tok0 + qi0 + otq * 4 + i;
#pragma unroll
        for (int c = 0; c < 4; c++) {
            float4 r;
            r.x = o[i][c].x * inv[i]; r.y = o[i][c].y * inv[i];
            r.z = o[i][c].z * inv[i]; r.w = o[i][c].w * inv[i];
            *(float4*)&outp[(size_t)token * ATTW + h * HD + (otd + 16 * c) * 4] = r;
        }
    }
}

// ---------------------------------------------------------------------------
extern "C" void kernel_launch(void* const* d_in, const int* in_sizes, int n_in,
                              void* d_out, int out_size)
{
    const float* hidden = (const float*)d_in[0];
    const float* cosb   = (const float*)d_in[1];
    const float* sinb   = (const float*)d_in[2];
    const float* w_qkv  = (const float*)d_in[3];
    const float* w_o    = (const float*)d_in[4];
    float* out = (float*)d_out;

    float *d_qkv, *d_att;
    cudaGetSymbolAddress((void**)&d_qkv, g_qkv);
    cudaGetSymbolAddress((void**)&d_att, g_att);
    __nv_bfloat16 *hH, *hL, *wqH, *wqL, *aH, *aL, *woH, *woL;
    cudaGetSymbolAddress((void**)&hH,  g_hidH);
    cudaGetSymbolAddress((void**)&hL,  g_hidL);
    cudaGetSymbolAddress((void**)&wqH, g_wqH);
    cudaGetSymbolAddress((void**)&wqL, g_wqL);
    cudaGetSymbolAddress((void**)&aH,  g_aH);
    cudaGetSymbolAddress((void**)&aL,  g_aL);
    cudaGetSymbolAddress((void**)&woH, g_woH);
    cudaGetSymbolAddress((void**)&woL, g_woL);

    cudaFuncSetAttribute(gemm_tc, cudaFuncAttributeMaxDynamicSharedMemorySize,
                         GEMM_SMEM);
    cudaFuncSetAttribute(attn_kernel, cudaFuncAttributeMaxDynamicSharedMemorySize,
                         ATT_SMEM_BYTES);

    // 0. split fp32 -> bf16 hi/lo for GEMM1 operands
    {
        size_t n1 = (size_t)TT * HIDDIM;
        size_t n2 = (size_t)QKVW * HIDDIM;
        split_bf16<<<(unsigned)((n1 / 4 + 255) / 256), 256>>>(hidden, hH, hL, n1);
        split_bf16<<<(unsigned)((n2 / 4 + 255) / 256), 256>>>(w_qkv, wqH, wqL, n2);
    }

    // 1. QKV projection (tensor cores): M=4096, N=8192, K=3584
    gemm_tc<<<dim3(QKVW / GBN, TT / GBM), 256, GEMM_SMEM>>>(
        hH, hL, wqH, wqL, d_qkv, TT, QKVW, HIDDIM);

    // 2. RoPE + transpose
    rope_transpose<<<dim3(TT, NH + NKV), 128>>>(cosb, sinb);

    // 3. Sliding-window attention
    attn_kernel<<<dim3(SEQ / BQ, NH, NB), 256, ATT_SMEM_BYTES>>>(d_att);

    // 4. split attention output + w_o
    {
        size_t n3 = (size_t)TT * ATTW;
        size_t n4 = (size_t)HIDDIM * ATTW;
        split_bf16<<<(unsigned)((n3 / 4 + 255) / 256), 256>>>(d_att, aH, aL, n3);
        split_bf16<<<(unsigned)((n4 / 4 + 255) / 256), 256>>>(w_o, woH, woL, n4);
    }

    // 5. Output projection (tensor cores): M=4096, N=3584, K=4096
    gemm_tc<<<dim3(HIDDIM / GBN, TT / GBM), 256, GEMM_SMEM>>>(
        aH, aL, woH, woL, out, TT, HIDDIM, ATTW);
}

// round 9
// speedup vs baseline: 1.7453x; 1.1017x over previous
#include <cuda_runtime.h>
#include <cuda_fp16.h>
#include <math.h>
#include <stdint.h>

#define TT     4096      // total tokens B*S
#define HIDDIM 3584
#define NH     16
#define NKV    8
#define HD     256
#define SEQ    2048
#define NB     2
#define QKVW   8192      // (NH + 2*NKV) * HD
#define ATTW   4096      // NH * HD
#define WIN    1024
#define QSCALE 0.0625f   // 256^-0.5
#define SOFTCAP 50.0f

#define BQ 64
#define BK 64

#define WSCALE 32.0f     // weight pre-scale so fp16 lo-plane stays normal
#define CSCALE (1.0f / 32.0f)

// ---------------- scratch (static device allocations) ----------------------
__device__ float g_qkv[(size_t)TT * QKVW];      // 128 MB fp32 qkv
__device__ float g_att[(size_t)TT * ATTW];      //  64 MB attention output
__device__ float g_qT[(size_t)NH * HD * TT];    //  [h][d][t] RoPE'd + scaled
__device__ float g_kT[(size_t)NKV * HD * TT];   //  [kh][d][t] RoPE'd

// fp16 split planes (hi + lo)
__device__ __half g_hidH[(size_t)TT * HIDDIM];
__device__ __half g_hidL[(size_t)TT * HIDDIM];
__device__ __half g_wqH[(size_t)QKVW * HIDDIM];
__device__ __half g_wqL[(size_t)QKVW * HIDDIM];
__device__ __half g_aH[(size_t)TT * ATTW];
__device__ __half g_aL[(size_t)TT * ATTW];
__device__ __half g_woH[(size_t)HIDDIM * ATTW];
__device__ __half g_woL[(size_t)HIDDIM * ATTW];

// ---------------------------------------------------------------------------
// fp32 -> fp16 hi/lo split (with pre-scale)
// ---------------------------------------------------------------------------
__global__ __launch_bounds__(256) void split_f16(
    const float* __restrict__ src,
    __half* __restrict__ hi, __half* __restrict__ lo, float scale, size_t n)
{
    size_t i = ((size_t)blockIdx.x * blockDim.x + threadIdx.x) * 4;
    if (i >= n) return;
    float4 v = *(const float4*)(src + i);
    v.x *= scale; v.y *= scale; v.z *= scale; v.w *= scale;
    __half h0 = __float2half(v.x), h1 = __float2half(v.y);
    __half h2 = __float2half(v.z), h3 = __float2half(v.w);
    __half l0 = __float2half(v.x - __half2float(h0));
    __half l1 = __float2half(v.y - __half2float(h1));
    __half l2 = __float2half(v.z - __half2float(h2));
    __half l3 = __float2half(v.w - __half2float(h3));
    *(__half2*)(hi + i)     = __halves2half2(h0, h1);
    *(__half2*)(hi + i + 2) = __halves2half2(h2, h3);
    *(__half2*)(lo + i)     = __halves2half2(l0, l1);
    *(__half2*)(lo + i + 2) = __halves2half2(l2, l3);
}

// ---------------------------------------------------------------------------
// mma.sync helpers (baseline PTX)
// ---------------------------------------------------------------------------
__device__ __forceinline__ uint32_t smem_u32(const void* p) {
    uint32_t a;
    asm("{ .reg .u64 t; cvta.to.shared.u64 t, %1; cvt.u32.u64 %0, t; }"
        : "=r"(a) : "l"(p));
    return a;
}
__device__ __forceinline__ void ldsm_x4(uint32_t* r, uint32_t addr) {
    asm volatile("ldmatrix.sync.aligned.m8n8.x4.shared.b16 {%0,%1,%2,%3}, [%4];"
                 : "=r"(r[0]), "=r"(r[1]), "=r"(r[2]), "=r"(r[3]) : "r"(addr));
}
__device__ __forceinline__ void mma_f16(float* c, const uint32_t* a,
                                        const uint32_t* b) {
    asm volatile(
        "mma.sync.aligned.m16n8k16.row.col.f32.f16.f16.f32 "
        "{%0,%1,%2,%3}, {%4,%5,%6,%7}, {%8,%9}, {%0,%1,%2,%3};"
        : "+f"(c[0]), "+f"(c[1]), "+f"(c[2]), "+f"(c[3])
        : "r"(a[0]), "r"(a[1]), "r"(a[2]), "r"(a[3]), "r"(b[0]), "r"(b[1]));
}

// ---------------------------------------------------------------------------
// Tensor-core GEMM (NT): C[m,n] = sum_k A[m,k]*B[n,k], fp32 via fp16 split.
// NPROD=3: AhBh + AhBl + AlBh. NPROD=2: AhBh + AlBh (B-lo plane not loaded).
// BM=128, BN=128, BK=32, 8 warps, 4-stage cp.async, rows padded to 80B.
// ---------------------------------------------------------------------------
#define GBM 128
#define GBN 128
#define GBKT 32
#define ROWB    80
#define PLANE_B (128 * ROWB)         // 10240 B
#define STAGE_B (4 * PLANE_B)        // 40960 B
#define NSTAGE  4
#define GEMM_SMEM (NSTAGE * STAGE_B) // 163840 B

template<int NPROD>
__global__ __launch_bounds__(256) void gemm_tc(
    const __half* __restrict__ Ah, const __half* __restrict__ Al,
    const __half* __restrict__ Bh, const __half* __restrict__ Bl,
    float* __restrict__ C, int n0, int N, int K, float cscale)
{
    extern __shared__ char smg[];
    const uint32_t sb = smem_u32(smg);
    const int tid  = threadIdx.x;
    const int lane = tid & 31;
    const int w    = tid >> 5;
    const int wm   = (w & 3) * 32;
    const int wn   = (w >> 2) * 64;
    const int bn0  = blockIdx.x * GBN + n0;
    const int bm0  = blockIdx.y * GBM;
    const int niter = K / GBKT;

    const __half* srcs[4] = { Ah, Al, Bh, Bl };
    const int NCH = (NPROD == 3) ? 8 : 6;   // 16B chunks / 256 threads

    auto load_stage = [&](int kt, int s) {
#pragma unroll
        for (int i = 0; i < NCH; i++) {
            int q    = tid + i * 256;
            int pl   = q >> 9;             // 0:Ah 1:Al 2:Bh 3:Bl
            int r    = q & 511;
            int row  = r >> 2;
            int slot = r & 3;
            int rb   = (pl < 2) ? bm0 : bn0;
            const __half* sp = srcs[pl]
                + (size_t)(rb + row) * K + kt * GBKT + slot * 8;
            uint32_t dst = sb + s * STAGE_B + pl * PLANE_B
                         + row * ROWB + slot * 16;
            asm volatile("cp.async.cg.shared.global [%0], [%1], 16;"
                         :: "r"(dst), "l"(sp));
        }
    };

    float acc[2][8][4];
#pragma unroll
    for (int mt = 0; mt < 2; mt++)
#pragma unroll
        for (int nt = 0; nt < 8; nt++)
#pragma unroll
            for (int e = 0; e < 4; e++) acc[mt][nt][e] = 0.f;

#pragma unroll
    for (int s = 0; s < NSTAGE - 1; s++) {
        load_stage(s, s);
        asm volatile("cp.async.commit_group;");
    }

    const int a_row  = lane & 15, a_half = (lane >> 4) * 8;
    const int b_row2 = (lane & 7) | ((lane >> 1) & 8);
    const int b_half = ((lane >> 3) & 1) * 8;

    for (int kt = 0; kt < niter; kt++) {
        asm volatile("cp.async.wait_group %0;" :: "n"(NSTAGE - 2));
        __syncthreads();

        if (kt + NSTAGE - 1 < niter)
            load_stage(kt + NSTAGE - 1, (kt + NSTAGE - 1) & (NSTAGE - 1));
        asm volatile("cp.async.commit_group;");

        const uint32_t sbase = sb + (kt & (NSTAGE - 1)) * STAGE_B;
#pragma unroll
        for (int ks = 0; ks < GBKT; ks += 16) {
            uint32_t ah[2][4], al[2][4];
#pragma unroll
            for (int mt = 0; mt < 2; mt++) {
                uint32_t aaddr = sbase + (wm + mt * 16 + a_row) * ROWB
                               + (ks + a_half) * 2;
                ldsm_x4(ah[mt], aaddr);
                ldsm_x4(al[mt], aaddr + PLANE_B);
            }
#pragma unroll
            for (int p = 0; p < 4; p++) {
                uint32_t baddr = sbase + 2 * PLANE_B
                               + (wn + p * 16 + b_row2) * ROWB
                               + (ks + b_half) * 2;
                uint32_t bh4[4], bl4[4];
                ldsm_x4(bh4, baddr);
                if (NPROD == 3) ldsm_x4(bl4, baddr + PLANE_B);
#pragma unroll
                for (int j = 0; j < 2; j++) {
                    int nt = p * 2 + j;
#pragma unroll
                    for (int mt = 0; mt < 2; mt++) {
                        mma_f16(acc[mt][nt], ah[mt], &bh4[2 * j]);
                        if (NPROD == 3)
                            mma_f16(acc[mt][nt], ah[mt], &bl4[2 * j]);
                        mma_f16(acc[mt][nt], al[mt], &bh4[2 * j]);
                    }
                }
            }
        }
        __syncthreads();
    }

    const int cr = lane >> 2, cc = (lane & 3) * 2;
#pragma unroll
    for (int mt = 0; mt < 2; mt++) {
#pragma unroll
        for (int nt = 0; nt < 8; nt++) {
            int row0 = bm0 + wm + mt * 16 + cr;
            int col  = bn0 + wn + nt * 8 + cc;
            *(float2*)&C[(size_t)row0 * N + col] =
                make_float2(acc[mt][nt][0] * cscale, acc[mt][nt][1] * cscale);
            *(float2*)&C[(size_t)(row0 + 8) * N + col] =
                make_float2(acc[mt][nt][2] * cscale, acc[mt][nt][3] * cscale);
        }
    }
}

// ---------------------------------------------------------------------------
// RoPE + transpose with smem tile transpose: coalesced reads AND writes.
// Block: 128 threads, 32 tokens x 256 d for one head.
// ---------------------------------------------------------------------------
__global__ __launch_bounds__(128) void rope_transpose(
    const float* __restrict__ cosb, const float* __restrict__ sinb)
{
    __shared__ float sm[32 * 257];          // [tk][d], pad 257
    const int hh = blockIdx.y;              // 0..15 q heads, 16..23 k heads
    const int t0 = blockIdx.x * 32;
    const int tid = threadIdx.x;
    const int tk = tid >> 2, sl = tid & 3;
    const int t = t0 + tk;
    const float* row = g_qkv + (size_t)t * QKVW + hh * HD;
    const bool isq = hh < NH;
    const float qs = isq ? QSCALE : 1.f;

#pragma unroll
    for (int c = 0; c < 4; c++) {
        int d = sl * 32 + c * 8;
        float u[8], v[8], cn[8], sn[8];
        *(float4*)(u)      = *(const float4*)(row + d);
        *(float4*)(u + 4)  = *(const float4*)(row + d + 4);
        *(float4*)(v)      = *(const float4*)(row + d + 128);
        *(float4*)(v + 4)  = *(const float4*)(row + d + 132);
        *(float4*)(cn)     = *(const float4*)(cosb + (size_t)t * 128 + d);
        *(float4*)(cn + 4) = *(const float4*)(cosb + (size_t)t * 128 + d + 4);
        *(float4*)(sn)     = *(const float4*)(sinb + (size_t)t * 128 + d);
        *(float4*)(sn + 4) = *(const float4*)(sinb + (size_t)t * 128 + d + 4);
#pragma unroll
        for (int i = 0; i < 8; i++) {
            sm[tk * 257 + d + i]       = (u[i] * cn[i] - v[i] * sn[i]) * qs;
            sm[tk * 257 + d + 128 + i] = (v[i] * cn[i] + u[i] * sn[i]) * qs;
        }
    }
    __syncthreads();

    float* dst = isq ? (g_qT + (size_t)hh * HD * TT)
                     : (g_kT + (size_t)(hh - NH) * HD * TT);
#pragma unroll
    for (int it = 0; it < 16; it++) {
        int r  = it * 16 + (tid >> 3);
        int tc = (tid & 7) * 4;
        float4 w4 = make_float4(sm[(tc + 0) * 257 + r], sm[(tc + 1) * 257 + r],
                                sm[(tc + 2) * 257 + r], sm[(tc + 3) * 257 + r]);
        *(float4*)(dst + (size_t)r * TT + t0 + tc) = w4;
    }
}

// ---------------------------------------------------------------------------
// Flash attention, fp32, Bq=Bk=64, online softmax, softcap+sliding window.
// ---------------------------------------------------------------------------
#define ST_LD 68
#define ATT_SMEM_FLOATS (16384*3 + 64*ST_LD + 192)
#define ATT_SMEM_BYTES  (ATT_SMEM_FLOATS * 4)

__global__ __launch_bounds__(256) void attn_kernel(float* __restrict__ outp)
{
    extern __shared__ float smf[];
    float* Qs   = smf;               // [256][64]
    float* Ks   = smf + 16384;       // [256][64]
    float* Vs   = smf + 32768;       // [64][256]
    float* St   = smf + 49152;       // [64][ST_LD]
    float* rowm = St + 64 * ST_LD;
    float* rowl = rowm + 64;
    float* alf  = rowl + 64;

    const int tid  = threadIdx.x;
    const int qt   = blockIdx.x, h = blockIdx.y, b = blockIdx.z;
    const int qi0  = qt * BQ;
    const int tok0 = b * SEQ;
    const int kh   = h >> 1;

    const float* qsrc = g_qT + (size_t)h * HD * TT + tok0 + qi0;
#pragma unroll
    for (int it = 0; it < 16; it++) {
        int idx = tid + it * 256;
        int d = idx >> 4, c4 = idx & 15;
        *(float4*)&Qs[d * 64 + c4 * 4] =
            *(const float4*)(qsrc + (size_t)d * TT + c4 * 4);
    }
    if (tid < 64) { rowm[tid] = -1e30f; rowl[tid] = 0.f; }

    const int otq = tid >> 4;
    const int otd = tid & 15;
    float4 o[4][4];
#pragma unroll
    for (int i = 0; i < 4; i++)
#pragma unroll
        for (int c = 0; c < 4; c++) o[i][c] = make_float4(0.f, 0.f, 0.f, 0.f);
    __syncthreads();

    const int kt0 = (qi0 - WIN > 0) ? (qi0 - WIN) : 0;
    for (int kj0 = kt0; kj0 <= qi0; kj0 += BK) {
        const float* ksrc = g_kT + (size_t)kh * HD * TT + tok0 + kj0;
#pragma unroll
        for (int it = 0; it < 16; it++) {
            int idx = tid + it * 256;
            int d = idx >> 4, c4 = idx & 15;
            *(float4*)&Ks[d * 64 + c4 * 4] =
                *(const float4*)(ksrc + (size_t)d * TT + c4 * 4);
        }
        const float* vsrc = g_qkv + (size_t)(tok0 + kj0) * QKVW
                          + (NH + NKV) * HD + kh * HD;
#pragma unroll
        for (int it = 0; it < 16; it++) {
            int idx = tid + it * 256;
            int kr = idx >> 6, d4 = idx & 63;
            *(float4*)&Vs[kr * 256 + d4 * 4] =
                *(const float4*)(vsrc + (size_t)kr * QKVW + d4 * 4);
        }
        __syncthreads();

        {
            const int tq = tid & 15, tk = tid >> 4;
            float s4[4][4];
#pragma unroll
            for (int i = 0; i < 4; i++)
#pragma unroll
                for (int j = 0; j < 4; j++) s4[i][j] = 0.f;
            for (int d = 0; d < HD; d++) {
                float a[4], bb[4];
                *(float4*)a  = *(const float4*)&Qs[d * 64 + tq * 4];
                *(float4*)bb = *(const float4*)&Ks[d * 64 + tk * 4];
#pragma unroll
                for (int i = 0; i < 4; i++)
#pragma unroll
                    for (int j = 0; j < 4; j++)
                        s4[i][j] = fmaf(a[i], bb[j], s4[i][j]);
            }
#pragma unroll
            for (int i = 0; i < 4; i++) {
#pragma unroll
                for (int j = 0; j < 4; j++) {
                    float sv = SOFTCAP * tanhf(s4[i][j] * (1.0f / SOFTCAP));
                    int ig = qi0 + tq * 4 + i;
                    int jg = kj0 + tk * 4 + j;
                    if (jg > ig || jg < ig - WIN) sv = -1e30f;
                    St[(tk * 4 + j) * ST_LD + tq * 4 + i] = sv;
                }
            }
        }
        __syncthreads();

        {
            int qr = tid >> 2, sub = tid & 3;
            float mx = -1e30f;
#pragma unroll
            for (int ii = 0; ii < 16; ii++)
                mx = fmaxf(mx, St[(sub * 16 + ii) * ST_LD + qr]);
            mx = fmaxf(mx, __shfl_xor_sync(0xffffffffu, mx, 1));
            mx = fmaxf(mx, __shfl_xor_sync(0xffffffffu, mx, 2));
            float mold = rowm[qr];
            float mnew = fmaxf(mold, mx);
            float al   = __expf(mold - mnew);
            float ps   = 0.f;
#pragma unroll
            for (int ii = 0; ii < 16; ii++) {
                int a = (sub * 16 + ii) * ST_LD + qr;
                float sv = St[a];
                float p  = (sv > -1e29f) ? __expf(sv - mnew) : 0.f;
                St[a] = p;
                ps += p;
            }
            ps += __shfl_xor_sync(0xffffffffu, ps, 1);
            ps += __shfl_xor_sync(0xffffffffu, ps, 2);
            if (sub == 0) {
                rowm[qr] = mnew;
                rowl[qr] = rowl[qr] * al + ps;
                alf[qr]  = al;
            }
        }
        __syncthreads();

        {
            float ar[4];
#pragma unroll
            for (int i = 0; i < 4; i++) ar[i] = alf[otq * 4 + i];
#pragma unroll
            for (int i = 0; i < 4; i++)
#pragma unroll
                for (int c = 0; c < 4; c++) {
                    o[i][c].x *= ar[i]; o[i][c].y *= ar[i];
                    o[i][c].z *= ar[i]; o[i][c].w *= ar[i];
                }
            for (int kc = 0; kc < BK; kc++) {
                float4 p4 = *(const float4*)&St[kc * ST_LD + otq * 4];
                float pr[4] = { p4.x, p4.y, p4.z, p4.w };
                float4 vv[4];
#pragma unroll
                for (int c = 0; c < 4; c++)
                    vv[c] = *(const float4*)&Vs[kc * 256 + (otd + 16 * c) * 4];
#pragma unroll
                for (int i = 0; i < 4; i++)
#pragma unroll
                    for (int c = 0; c < 4; c++) {
                        o[i][c].x = fmaf(pr[i], vv[c].x, o[i][c].x);
                        o[i][c].y = fmaf(pr[i], vv[c].y, o[i][c].y);
                        o[i][c].z = fmaf(pr[i], vv[c].z, o[i][c].z);
                        o[i][c].w = fmaf(pr[i], vv[c].w, o[i][c].w);
                    }
            }
        }
        __syncthreads();
    }

    float inv[4];
#pragma unroll
    for (int i = 0; i < 4; i++) inv[i] = 1.0f / rowl[otq * 4 + i];
#pragma unroll
    for (int i = 0; i < 4; i++) {
        int token = tok0 + qi0 + otq * 4 + i;
#pragma unroll
        for (int c = 0; c < 4; c++) {
            float4 r;
            r.x = o[i][c].x * inv[i]; r.y = o[i][c].y * inv[i];
            r.z = o[i][c].z * inv[i]; r.w = o[i][c].w * inv[i];
            *(float4*)&outp[(size_t)token * ATTW + h * HD + (otd + 16 * c) * 4] = r;
        }
    }
}

// ---------------------------------------------------------------------------
extern "C" void kernel_launch(void* const* d_in, const int* in_sizes, int n_in,
                              void* d_out, int out_size)
{
    const float* hidden = (const float*)d_in[0];
    const float* cosb   = (const float*)d_in[1];
    const float* sinb   = (const float*)d_in[2];
    const float* w_qkv  = (const float*)d_in[3];
    const float* w_o    = (const float*)d_in[4];
    float* out = (float*)d_out;

    float *d_qkv, *d_att;
    cudaGetSymbolAddress((void**)&d_qkv, g_qkv);
    cudaGetSymbolAddress((void**)&d_att, g_att);
    __half *hH, *hL, *wqH, *wqL, *aH, *aL, *woH, *woL;
    cudaGetSymbolAddress((void**)&hH,  g_hidH);
    cudaGetSymbolAddress((void**)&hL,  g_hidL);
    cudaGetSymbolAddress((void**)&wqH, g_wqH);
    cudaGetSymbolAddress((void**)&wqL, g_wqL);
    cudaGetSymbolAddress((void**)&aH,  g_aH);
    cudaGetSymbolAddress((void**)&aL,  g_aL);
    cudaGetSymbolAddress((void**)&woH, g_woH);
    cudaGetSymbolAddress((void**)&woL, g_woL);

    cudaFuncSetAttribute(gemm_tc<3>, cudaFuncAttributeMaxDynamicSharedMemorySize,
                         GEMM_SMEM);
    cudaFuncSetAttribute(gemm_tc<2>, cudaFuncAttributeMaxDynamicSharedMemorySize,
                         GEMM_SMEM);
    cudaFuncSetAttribute(attn_kernel, cudaFuncAttributeMaxDynamicSharedMemorySize,
                         ATT_SMEM_BYTES);

    // 0. split fp32 -> fp16 hi/lo (weights pre-scaled x32)
    {
        size_t n1 = (size_t)TT * HIDDIM;
        size_t n2 = (size_t)QKVW * HIDDIM;
        split_f16<<<(unsigned)((n1 / 4 + 255) / 256), 256>>>(hidden, hH, hL, 1.0f, n1);
        split_f16<<<(unsigned)((n2 / 4 + 255) / 256), 256>>>(w_qkv, wqH, wqL, WSCALE, n2);
    }

    // 1. QKV projection: Q+K columns (3-product, precision-critical),
    //                    V columns (2-product)
    gemm_tc<3><<<dim3(6144 / GBN, TT / GBM), 256, GEMM_SMEM>>>(
        hH, hL, wqH, wqL, d_qkv, 0, QKVW, HIDDIM, CSCALE);
    gemm_tc<2><<<dim3(2048 / GBN, TT / GBM), 256, GEMM_SMEM>>>(
        hH, hL, wqH, wqL, d_qkv, 6144, QKVW, HIDDIM, CSCALE);

    // 2. RoPE + transpose (smem tile transpose, coalesced writes)
    rope_transpose<<<dim3(TT / 32, NH + NKV), 128>>>(cosb, sinb);

    // 3. Sliding-window attention
    attn_kernel<<<dim3(SEQ / BQ, NH, NB), 256, ATT_SMEM_BYTES>>>(d_att);

    // 4. split attention output + w_o
    {
        size_t n3 = (size_t)TT * ATTW;
        size_t n4 = (size_t)HIDDIM * ATTW;
        split_f16<<<(unsigned)((n3 / 4 + 255) / 256), 256>>>(d_att, aH, aL, 1.0f, n3);
        split_f16<<<(unsigned)((n4 / 4 + 255) / 256), 256>>>(w_o, woH, woL, WSCALE, n4);
    }

    // 5. Output projection (2-product)
    gemm_tc<2><<<dim3(HIDDIM / GBN, TT / GBM), 256, GEMM_SMEM>>>(
        aH, aL, woH, woL, out, 0, HIDDIM, ATTW, CSCALE);
}

// round 13
// speedup vs baseline: 1.8090x; 1.0365x over previous
#include <cuda_runtime.h>
#include <cuda_fp16.h>
#include <math.h>
#include <stdint.h>

#define TT     4096      // total tokens B*S
#define HIDDIM 3584
#define NH     16
#define NKV    8
#define HD     256
#define SEQ    2048
#define NB     2
#define QKVW   8192      // (NH + 2*NKV) * HD
#define ATTW   4096      // NH * HD
#define WIN    1024
#define QSCALE 0.0625f   // 256^-0.5
#define SOFTCAP 50.0f

#define BQ 64
#define BK 64

#define WSCALE 32.0f     // weight pre-scale so fp16 lo-plane stays normal
#define CSCALE (1.0f / 32.0f)

// ---------------- scratch (static device allocations) ----------------------
__device__ float g_qkv[(size_t)TT * QKVW];
__device__ float g_att[(size_t)TT * ATTW];
__device__ float g_qT[(size_t)NH * HD * TT];
__device__ float g_kT[(size_t)NKV * HD * TT];

__device__ __half g_hidH[(size_t)TT * HIDDIM];
__device__ __half g_hidL[(size_t)TT * HIDDIM];
__device__ __half g_wqH[(size_t)QKVW * HIDDIM];
__device__ __half g_wqL[(size_t)QKVW * HIDDIM];
__device__ __half g_aH[(size_t)TT * ATTW];
__device__ __half g_aL[(size_t)TT * ATTW];
__device__ __half g_woH[(size_t)HIDDIM * ATTW];
__device__ __half g_woL[(size_t)HIDDIM * ATTW];

// ---------------------------------------------------------------------------
// fp32 -> fp16 hi/lo split (with pre-scale)
// ---------------------------------------------------------------------------
__global__ __launch_bounds__(256) void split_f16(
    const float* __restrict__ src,
    __half* __restrict__ hi, __half* __restrict__ lo, float scale, size_t n)
{
    size_t i = ((size_t)blockIdx.x * blockDim.x + threadIdx.x) * 4;
    if (i >= n) return;
    float4 v = *(const float4*)(src + i);
    v.x *= scale; v.y *= scale; v.z *= scale; v.w *= scale;
    __half h0 = __float2half(v.x), h1 = __float2half(v.y);
    __half h2 = __float2half(v.z), h3 = __float2half(v.w);
    __half l0 = __float2half(v.x - __half2float(h0));
    __half l1 = __float2half(v.y - __half2float(h1));
    __half l2 = __float2half(v.z - __half2float(h2));
    __half l3 = __float2half(v.w - __half2float(h3));
    *(__half2*)(hi + i)     = __halves2half2(h0, h1);
    *(__half2*)(hi + i + 2) = __halves2half2(h2, h3);
    *(__half2*)(lo + i)     = __halves2half2(l0, l1);
    *(__half2*)(lo + i + 2) = __halves2half2(l2, l3);
}

// ---------------------------------------------------------------------------
// mma.sync helpers
// ---------------------------------------------------------------------------
__device__ __forceinline__ uint32_t smem_u32(const void* p) {
    uint32_t a;
    asm("{ .reg .u64 t; cvta.to.shared.u64 t, %1; cvt.u32.u64 %0, t; }"
        : "=r"(a) : "l"(p));
    return a;
}
__device__ __forceinline__ void ldsm_x4(uint32_t* r, uint32_t addr) {
    asm volatile("ldmatrix.sync.aligned.m8n8.x4.shared.b16 {%0,%1,%2,%3}, [%4];"
                 : "=r"(r[0]), "=r"(r[1]), "=r"(r[2]), "=r"(r[3]) : "r"(addr));
}
__device__ __forceinline__ void mma_f16(float* c, const uint32_t* a,
                                        const uint32_t* b) {
    asm volatile(
        "mma.sync.aligned.m16n8k16.row.col.f32.f16.f16.f32 "
        "{%0,%1,%2,%3}, {%4,%5,%6,%7}, {%8,%9}, {%0,%1,%2,%3};"
        : "+f"(c[0]), "+f"(c[1]), "+f"(c[2]), "+f"(c[3])
        : "r"(a[0]), "r"(a[1]), "r"(a[2]), "r"(a[3]), "r"(b[0]), "r"(b[1]));
}

// ---------------------------------------------------------------------------
// Tensor-core GEMM (NT): C[m,n] = sum_k A[m,k]*B[n,k], fp32 via fp16 split.
// NPROD=3: AhBh + AhBl + AlBh. NPROD=2: AhBh + AlBh (no Bl plane at all).
// BM=128, BN=256, BK=32, 512 threads (16 warps, warp tile 32x64).
// NPROD=3: 3-stage pipeline (60KB/stage); NPROD=2: 4-stage (40KB/stage).
// ---------------------------------------------------------------------------
#define GBM 128
#define GBN 256
#define GBKT 32
#define ROWB    80                    // padded row bytes (32 fp16 + 8 pad)
#define APL_B   (128 * ROWB)          // 10240 : one A plane
#define BPL_B   (256 * ROWB)          // 20480 : one B plane

template<int NPROD>
__global__ __launch_bounds__(512) void gemm_tc(
    const __half* __restrict__ Ah, const __half* __restrict__ Al,
    const __half* __restrict__ Bh, const __half* __restrict__ Bl,
    float* __restrict__ C, int n0, int N, int K, float cscale)
{
    constexpr int STAGE_B = (NPROD == 3) ? (2 * APL_B + 2 * BPL_B)
                                         : (2 * APL_B + BPL_B);
    constexpr int NSTAGE  = (NPROD == 3) ? 3 : 4;

    extern __shared__ char smg[];
    const uint32_t sb = smem_u32(smg);
    const int tid  = threadIdx.x;
    const int lane = tid & 31;
    const int w    = tid >> 5;           // 0..15
    const int wm   = (w & 3) * 32;
    const int wn   = (w >> 2) * 64;
    const int bn0  = blockIdx.x * GBN + n0;
    const int bm0  = blockIdx.y * GBM;
    const int niter = K / GBKT;

    auto load_stage = [&](int kt, int s) {
        const int NCH = (NPROD == 3) ? 6 : 4;   // 16B chunks / 512 threads
#pragma unroll
        for (int i = 0; i < NCH; i++) {
            int q = tid + i * 512;
            uint32_t dst;
            const __half* sp;
            if (q < 1024) {                    // A planes
                int pl = q >> 9;
                int r  = q & 511;
                int row = r >> 2, slot = r & 3;
                sp = (pl ? Al : Ah) + (size_t)(bm0 + row) * K
                   + kt * GBKT + slot * 8;
                dst = sb + s * STAGE_B + pl * APL_B + row * ROWB + slot * 16;
            } else {                           // B planes
                int qb = q - 1024;
                int pl = (NPROD == 3) ? (qb >> 10) : 0;
                int r  = qb & 1023;
                int row = r >> 2, slot = r & 3;
                sp = (pl ? Bl : Bh) + (size_t)(bn0 + row) * K
                   + kt * GBKT + slot * 8;
                dst = sb + s * STAGE_B + 2 * APL_B + pl * BPL_B
                    + row * ROWB + slot * 16;
            }
            asm volatile("cp.async.cg.shared.global [%0], [%1], 16;"
                         :: "r"(dst), "l"(sp));
        }
    };

    float acc[2][8][4];
#pragma unroll
    for (int mt = 0; mt < 2; mt++)
#pragma unroll
        for (int nt = 0; nt < 8; nt++)
#pragma unroll
            for (int e = 0; e < 4; e++) acc[mt][nt][e] = 0.f;

#pragma unroll
    for (int s = 0; s < NSTAGE - 1; s++) {
        load_stage(s, s);
        asm volatile("cp.async.commit_group;");
    }

    const int a_row  = lane & 15, a_half = (lane >> 4) * 8;
    const int b_row2 = (lane & 7) | ((lane >> 1) & 8);
    const int b_half = ((lane >> 3) & 1) * 8;

    int cs = 0;                      // compute stage index
    int ls = NSTAGE - 1;             // next load stage index
    for (int kt = 0; kt < niter; kt++) {
        asm volatile("cp.async.wait_group %0;" :: "n"(NSTAGE - 2));
        __syncthreads();

        if (kt + NSTAGE - 1 < niter)
            load_stage(kt + NSTAGE - 1, ls);
        asm volatile("cp.async.commit_group;");
        if (++ls == NSTAGE) ls = 0;

        const uint32_t sbase = sb + cs * STAGE_B;
        if (++cs == NSTAGE) cs = 0;
#pragma unroll
        for (int ks = 0; ks < GBKT; ks += 16) {
            uint32_t ah[2][4], al[2][4];
#pragma unroll
            for (int mt = 0; mt < 2; mt++) {
                uint32_t aaddr = sbase + (wm + mt * 16 + a_row) * ROWB
                               + (ks + a_half) * 2;
                ldsm_x4(ah[mt], aaddr);
                ldsm_x4(al[mt], aaddr + APL_B);
            }
#pragma unroll
            for (int p = 0; p < 4; p++) {
                uint32_t baddr = sbase + 2 * APL_B
                               + (wn + p * 16 + b_row2) * ROWB
                               + (ks + b_half) * 2;
                uint32_t bh4[4], bl4[4];
                ldsm_x4(bh4, baddr);
                if (NPROD == 3) ldsm_x4(bl4, baddr + BPL_B);
#pragma unroll
                for (int j = 0; j < 2; j++) {
                    int nt = p * 2 + j;
#pragma unroll
                    for (int mt = 0; mt < 2; mt++) {
                        mma_f16(acc[mt][nt], ah[mt], &bh4[2 * j]);
                        if (NPROD == 3)
                            mma_f16(acc[mt][nt], ah[mt], &bl4[2 * j]);
                        mma_f16(acc[mt][nt], al[mt], &bh4[2 * j]);
                    }
                }
            }
        }
        __syncthreads();
    }

    const int cr = lane >> 2, cc = (lane & 3) * 2;
#pragma unroll
    for (int mt = 0; mt < 2; mt++) {
#pragma unroll
        for (int nt = 0; nt < 8; nt++) {
            int row0 = bm0 + wm + mt * 16 + cr;
            int col  = bn0 + wn + nt * 8 + cc;
            *(float2*)&C[(size_t)row0 * N + col] =
                make_float2(acc[mt][nt][0] * cscale, acc[mt][nt][1] * cscale);
            *(float2*)&C[(size_t)(row0 + 8) * N + col] =
                make_float2(acc[mt][nt][2] * cscale, acc[mt][nt][3] * cscale);
        }
    }
}

#define GEMM_SMEM3 (3 * (2 * APL_B + 2 * BPL_B))   // 184320
#define GEMM_SMEM2 (4 * (2 * APL_B + BPL_B))       // 163840

// ---------------------------------------------------------------------------
// RoPE + transpose with smem tile transpose
// ---------------------------------------------------------------------------
__global__ __launch_bounds__(128) void rope_transpose(
    const float* __restrict__ cosb, const float* __restrict__ sinb)
{
    __shared__ float sm[32 * 257];
    const int hh = blockIdx.y;
    const int t0 = blockIdx.x * 32;
    const int tid = threadIdx.x;
    const int tk = tid >> 2, sl = tid & 3;
    const int t = t0 + tk;
    const float* row = g_qkv + (size_t)t * QKVW + hh * HD;
    const bool isq = hh < NH;
    const float qs = isq ? QSCALE : 1.f;

#pragma unroll
    for (int c = 0; c < 4; c++) {
        int d = sl * 32 + c * 8;
        float u[8], v[8], cn[8], sn[8];
        *(float4*)(u)      = *(const float4*)(row + d);
        *(float4*)(u + 4)  = *(const float4*)(row + d + 4);
        *(float4*)(v)      = *(const float4*)(row + d + 128);
        *(float4*)(v + 4)  = *(const float4*)(row + d + 132);
        *(float4*)(cn)     = *(const float4*)(cosb + (size_t)t * 128 + d);
        *(float4*)(cn + 4) = *(const float4*)(cosb + (size_t)t * 128 + d + 4);
        *(float4*)(sn)     = *(const float4*)(sinb + (size_t)t * 128 + d);
        *(float4*)(sn + 4) = *(const float4*)(sinb + (size_t)t * 128 + d + 4);
#pragma unroll
        for (int i = 0; i < 8; i++) {
            sm[tk * 257 + d + i]       = (u[i] * cn[i] - v[i] * sn[i]) * qs;
            sm[tk * 257 + d + 128 + i] = (v[i] * cn[i] + u[i] * sn[i]) * qs;
        }
    }
    __syncthreads();

    float* dst = isq ? (g_qT + (size_t)hh * HD * TT)
                     : (g_kT + (size_t)(hh - NH) * HD * TT);
#pragma unroll
    for (int it = 0; it < 16; it++) {
        int r  = it * 16 + (tid >> 3);
        int tc = (tid & 7) * 4;
        float4 w4 = make_float4(sm[(tc + 0) * 257 + r], sm[(tc + 1) * 257 + r],
                                sm[(tc + 2) * 257 + r], sm[(tc + 3) * 257 + r]);
        *(float4*)(dst + (size_t)r * TT + t0 + tc) = w4;
    }
}

// ---------------------------------------------------------------------------
// Flash attention, fp32, Bq=Bk=64, online softmax, softcap+sliding window.
// ---------------------------------------------------------------------------
#define ST_LD 68
#define ATT_SMEM_FLOATS (16384*3 + 64*ST_LD + 192)
#define ATT_SMEM_BYTES  (ATT_SMEM_FLOATS * 4)

__global__ __launch_bounds__(256) void attn_kernel(float* __restrict__ outp)
{
    extern __shared__ float smf[];
    float* Qs   = smf;
    float* Ks   = smf + 16384;
    float* Vs   = smf + 32768;
    float* St   = smf + 49152;
    float* rowm = St + 64 * ST_LD;
    float* rowl = rowm + 64;
    float* alf  = rowl + 64;

    const int tid  = threadIdx.x;
    const int qt   = blockIdx.x, h = blockIdx.y, b = blockIdx.z;
    const int qi0  = qt * BQ;
    const int tok0 = b * SEQ;
    const int kh   = h >> 1;

    const float* qsrc = g_qT + (size_t)h * HD * TT + tok0 + qi0;
#pragma unroll
    for (int it = 0; it < 16; it++) {
        int idx = tid + it * 256;
        int d = idx >> 4, c4 = idx & 15;
        *(float4*)&Qs[d * 64 + c4 * 4] =
            *(const float4*)(qsrc + (size_t)d * TT + c4 * 4);
    }
    if (tid < 64) { rowm[tid] = -1e30f; rowl[tid] = 0.f; }

    const int otq = tid >> 4;
    const int otd = tid & 15;
    float4 o[4][4];
#pragma unroll
    for (int i = 0; i < 4; i++)
#pragma unroll
        for (int c = 0; c < 4; c++) o[i][c] = make_float4(0.f, 0.f, 0.f, 0.f);
    __syncthreads();

    const int kt0 = (qi0 - WIN > 0) ? (qi0 - WIN) : 0;
    for (int kj0 = kt0; kj0 <= qi0; kj0 += BK) {
        const float* ksrc = g_kT + (size_t)kh * HD * TT + tok0 + kj0;
#pragma unroll
        for (int it = 0; it < 16; it++) {
            int idx = tid + it * 256;
            int d = idx >> 4, c4 = idx & 15;
            *(float4*)&Ks[d * 64 + c4 * 4] =
                *(const float4*)(ksrc + (size_t)d * TT + c4 * 4);
        }
        const float* vsrc = g_qkv + (size_t)(tok0 + kj0) * QKVW
                          + (NH + NKV) * HD + kh * HD;
#pragma unroll
        for (int it = 0; it < 16; it++) {
            int idx = tid + it * 256;
            int kr = idx >> 6, d4 = idx & 63;
            *(float4*)&Vs[kr * 256 + d4 * 4] =
                *(const float4*)(vsrc + (size_t)kr * QKVW + d4 * 4);
        }
        __syncthreads();

        {
            const int tq = tid & 15, tk = tid >> 4;
            float s4[4][4];
#pragma unroll
            for (int i = 0; i < 4; i++)
#pragma unroll
                for (int j = 0; j < 4; j++) s4[i][j] = 0.f;
            for (int d = 0; d < HD; d++) {
                float a[4], bb[4];
                *(float4*)a  = *(const float4*)&Qs[d * 64 + tq * 4];
                *(float4*)bb = *(const float4*)&Ks[d * 64 + tk * 4];
#pragma unroll
                for (int i = 0; i < 4; i++)
#pragma unroll
                    for (int j = 0; j < 4; j++)
                        s4[i][j] = fmaf(a[i], bb[j], s4[i][j]);
            }
#pragma unroll
            for (int i = 0; i < 4; i++) {
#pragma unroll
                for (int j = 0; j < 4; j++) {
                    float sv = SOFTCAP * tanhf(s4[i][j] * (1.0f / SOFTCAP));
                    int ig = qi0 + tq * 4 + i;
                    int jg = kj0 + tk * 4 + j;
                    if (jg > ig || jg < ig - WIN) sv = -1e30f;
                    St[(tk * 4 + j) * ST_LD + tq * 4 + i] = sv;
                }
            }
        }
        __syncthreads();

        {
            int qr = tid >> 2, sub = tid & 3;
            float mx = -1e30f;
#pragma unroll
            for (int ii = 0; ii < 16; ii++)
                mx = fmaxf(mx, St[(sub * 16 + ii) * ST_LD + qr]);
            mx = fmaxf(mx, __shfl_xor_sync(0xffffffffu, mx, 1));
            mx = fmaxf(mx, __shfl_xor_sync(0xffffffffu, mx, 2));
            float mold = rowm[qr];
            float mnew = fmaxf(mold, mx);
            float al   = __expf(mold - mnew);
            float ps   = 0.f;
#pragma unroll
            for (int ii = 0; ii < 16; ii++) {
                int a = (sub * 16 + ii) * ST_LD + qr;
                float sv = St[a];
                float p  = (sv > -1e29f) ? __expf(sv - mnew) : 0.f;
                St[a] = p;
                ps += p;
            }
            ps += __shfl_xor_sync(0xffffffffu, ps, 1);
            ps += __shfl_xor_sync(0xffffffffu, ps, 2);
            if (sub == 0) {
                rowm[qr] = mnew;
                rowl[qr] = rowl[qr] * al + ps;
                alf[qr]  = al;
            }
        }
        __syncthreads();

        {
            float ar[4];
#pragma unroll
            for (int i = 0; i < 4; i++) ar[i] = alf[otq * 4 + i];
#pragma unroll
            for (int i = 0; i < 4; i++)
#pragma unroll
                for (int c = 0; c < 4; c++) {
                    o[i][c].x *= ar[i]; o[i][c].y *= ar[i];
                    o[i][c].z *= ar[i]; o[i][c].w *= ar[i];
                }
            for (int kc = 0; kc < BK; kc++) {
                float4 p4 = *(const float4*)&St[kc * ST_LD + otq * 4];
                float pr[4] = { p4.x, p4.y, p4.z, p4.w };
                float4 vv[4];
#pragma unroll
                for (int c = 0; c < 4; c++)
                    vv[c] = *(const float4*)&Vs[kc * 256 + (otd + 16 * c) * 4];
#pragma unroll
                for (int i = 0; i < 4; i++)
#pragma unroll
                    for (int c = 0; c < 4; c++) {
                        o[i][c].x = fmaf(pr[i], vv[c].x, o[i][c].x);
                        o[i][c].y = fmaf(pr[i], vv[c].y, o[i][c].y);
                        o[i][c].z = fmaf(pr[i], vv[c].z, o[i][c].z);
                        o[i][c].w = fmaf(pr[i], vv[c].w, o[i][c].w);
                    }
            }
        }
        __syncthreads();
    }

    float inv[4];
#pragma unroll
    for (int i = 0; i < 4; i++) inv[i] = 1.0f / rowl[otq * 4 + i];
#pragma unroll
    for (int i = 0; i < 4; i++) {
        int token = tok0 + qi0 + otq * 4 + i;
#pragma unroll
        for (int c = 0; c < 4; c++) {
            float4 r;
            r.x = o[i][c].x * inv[i]; r.y = o[i][c].y * inv[i];
            r.z = o[i][c].z * inv[i]; r.w = o[i][c].w * inv[i];
            *(float4*)&outp[(size_t)token * ATTW + h * HD + (otd + 16 * c) * 4] = r;
        }
    }
}

// ---------------------------------------------------------------------------
extern "C" void kernel_launch(void* const* d_in, const int* in_sizes, int n_in,
                              void* d_out, int out_size)
{
    const float* hidden = (const float*)d_in[0];
    const float* cosb   = (const float*)d_in[1];
    const float* sinb   = (const float*)d_in[2];
    const float* w_qkv  = (const float*)d_in[3];
    const float* w_o    = (const float*)d_in[4];
    float* out = (float*)d_out;

    float *d_qkv, *d_att;
    cudaGetSymbolAddress((void**)&d_qkv, g_qkv);
    cudaGetSymbolAddress((void**)&d_att, g_att);
    __half *hH, *hL, *wqH, *wqL, *aH, *aL, *woH, *woL;
    cudaGetSymbolAddress((void**)&hH,  g_hidH);
    cudaGetSymbolAddress((void**)&hL,  g_hidL);
    cudaGetSymbolAddress((void**)&wqH, g_wqH);
    cudaGetSymbolAddress((void**)&wqL, g_wqL);
    cudaGetSymbolAddress((void**)&aH,  g_aH);
    cudaGetSymbolAddress((void**)&aL,  g_aL);
    cudaGetSymbolAddress((void**)&woH, g_woH);
    cudaGetSymbolAddress((void**)&woL, g_woL);

    cudaFuncSetAttribute(gemm_tc<3>, cudaFuncAttributeMaxDynamicSharedMemorySize,
                         GEMM_SMEM3);
    cudaFuncSetAttribute(gemm_tc<2>, cudaFuncAttributeMaxDynamicSharedMemorySize,
                         GEMM_SMEM2);
    cudaFuncSetAttribute(attn_kernel, cudaFuncAttributeMaxDynamicSharedMemorySize,
                         ATT_SMEM_BYTES);

    // 0. split fp32 -> fp16 hi/lo (weights pre-scaled x32)
    {
        size_t n1 = (size_t)TT * HIDDIM;
        size_t n2 = (size_t)QKVW * HIDDIM;
        split_f16<<<(unsigned)((n1 / 4 + 255) / 256), 256>>>(hidden, hH, hL, 1.0f, n1);
        split_f16<<<(unsigned)((n2 / 4 + 255) / 256), 256>>>(w_qkv, wqH, wqL, WSCALE, n2);
    }

    // 1. QKV projection: Q+K columns (3-product), V columns (2-product)
    gemm_tc<3><<<dim3(6144 / GBN, TT / GBM), 512, GEMM_SMEM3>>>(
        hH, hL, wqH, wqL, d_qkv, 0, QKVW, HIDDIM, CSCALE);
    gemm_tc<2><<<dim3(2048 / GBN, TT / GBM), 512, GEMM_SMEM2>>>(
        hH, hL, wqH, wqL, d_qkv, 6144, QKVW, HIDDIM, CSCALE);

    // 2. RoPE + transpose
    rope_transpose<<<dim3(TT / 32, NH + NKV), 128>>>(cosb, sinb);

    // 3. Sliding-window attention
    attn_kernel<<<dim3(SEQ / BQ, NH, NB), 256, ATT_SMEM_BYTES>>>(d_att);

    // 4. split attention output + w_o
    {
        size_t n3 = (size_t)TT * ATTW;
        size_t n4 = (size_t)HIDDIM * ATTW;
        split_f16<<<(unsigned)((n3 / 4 + 255) / 256), 256>>>(d_att, aH, aL, 1.0f, n3);
        split_f16<<<(unsigned)((n4 / 4 + 255) / 256), 256>>>(w_o, woH, woL, WSCALE, n4);
    }

    // 5. Output projection (2-product)
    gemm_tc<2><<<dim3(HIDDIM / GBN, TT / GBM), 512, GEMM_SMEM2>>>(
        aH, aL, woH, woL, out, 0, HIDDIM, ATTW, CSCALE);
}

// round 14
// speedup vs baseline: 2.3846x; 1.3182x over previous
#include <cuda_runtime.h>
#include <cuda_fp16.h>
#include <math.h>
#include <stdint.h>

#define TT     4096      // total tokens B*S
#define HIDDIM 3584
#define NH     16
#define NKV    8
#define HD     256
#define SEQ    2048
#define NB     2
#define QKVW   8192      // (NH + 2*NKV) * HD
#define ATTW   4096      // NH * HD
#define WIN    1024
#define SCALE  0.0625f   // 256^-0.5
#define SOFTCAP 50.0f

#define BQ 64
#define BK 64

#define WSCALE 32.0f
#define CSCALE (1.0f / 32.0f)

// ---------------- scratch (static device allocations) ----------------------
__device__ float g_qkv[(size_t)TT * QKVW];

// fp16 attention operand planes, layout [head][t][d]
__device__ __half g_qh[(size_t)NH * TT * HD];
__device__ __half g_ql[(size_t)NH * TT * HD];
__device__ __half g_kh[(size_t)NKV * TT * HD];
__device__ __half g_kl[(size_t)NKV * TT * HD];
__device__ __half g_vh[(size_t)NKV * TT * HD];
__device__ __half g_vl[(size_t)NKV * TT * HD];

// fp16 split planes for projections
__device__ __half g_hidH[(size_t)TT * HIDDIM];
__device__ __half g_hidL[(size_t)TT * HIDDIM];
__device__ __half g_wqH[(size_t)QKVW * HIDDIM];
__device__ __half g_wqL[(size_t)QKVW * HIDDIM];
__device__ __half g_aH[(size_t)TT * ATTW];
__device__ __half g_aL[(size_t)TT * ATTW];
__device__ __half g_woH[(size_t)HIDDIM * ATTW];
__device__ __half g_woL[(size_t)HIDDIM * ATTW];

// ---------------------------------------------------------------------------
// fp32 -> fp16 hi/lo split (with pre-scale)
// ---------------------------------------------------------------------------
__global__ __launch_bounds__(256) void split_f16(
    const float* __restrict__ src,
    __half* __restrict__ hi, __half* __restrict__ lo, float scale, size_t n)
{
    size_t i = ((size_t)blockIdx.x * blockDim.x + threadIdx.x) * 4;
    if (i >= n) return;
    float4 v = *(const float4*)(src + i);
    v.x *= scale; v.y *= scale; v.z *= scale; v.w *= scale;
    __half h0 = __float2half(v.x), h1 = __float2half(v.y);
    __half h2 = __float2half(v.z), h3 = __float2half(v.w);
    __half l0 = __float2half(v.x - __half2float(h0));
    __half l1 = __float2half(v.y - __half2float(h1));
    __half l2 = __float2half(v.z - __half2float(h2));
    __half l3 = __float2half(v.w - __half2float(h3));
    *(__half2*)(hi + i)     = __halves2half2(h0, h1);
    *(__half2*)(hi + i + 2) = __halves2half2(h2, h3);
    *(__half2*)(lo + i)     = __halves2half2(l0, l1);
    *(__half2*)(lo + i + 2) = __halves2half2(l2, l3);
}

// ---------------------------------------------------------------------------
// helpers
// ---------------------------------------------------------------------------
__device__ __forceinline__ uint32_t smem_u32(const void* p) {
    uint32_t a;
    asm("{ .reg .u64 t; cvta.to.shared.u64 t, %1; cvt.u32.u64 %0, t; }"
        : "=r"(a) : "l"(p));
    return a;
}
__device__ __forceinline__ void ldsm_x4(uint32_t* r, uint32_t addr) {
    asm volatile("ldmatrix.sync.aligned.m8n8.x4.shared.b16 {%0,%1,%2,%3}, [%4];"
                 : "=r"(r[0]), "=r"(r[1]), "=r"(r[2]), "=r"(r[3]) : "r"(addr));
}
__device__ __forceinline__ void ldsm_x4t(uint32_t* r, uint32_t addr) {
    asm volatile("ldmatrix.sync.aligned.m8n8.x4.trans.shared.b16 {%0,%1,%2,%3}, [%4];"
                 : "=r"(r[0]), "=r"(r[1]), "=r"(r[2]), "=r"(r[3]) : "r"(addr));
}
__device__ __forceinline__ void mma_f16(float* c, const uint32_t* a,
                                        const uint32_t* b) {
    asm volatile(
        "mma.sync.aligned.m16n8k16.row.col.f32.f16.f16.f32 "
        "{%0,%1,%2,%3}, {%4,%5,%6,%7}, {%8,%9}, {%0,%1,%2,%3};"
        : "+f"(c[0]), "+f"(c[1]), "+f"(c[2]), "+f"(c[3])
        : "r"(a[0]), "r"(a[1]), "r"(a[2]), "r"(a[3]), "r"(b[0]), "r"(b[1]));
}
__device__ __forceinline__ void cpa16(uint32_t dst, const void* src) {
    asm volatile("cp.async.cg.shared.global [%0], [%1], 16;"
                 :: "r"(dst), "l"(src));
}

// ---------------------------------------------------------------------------
// Tensor-core GEMM (NT), unchanged from R13.
// ---------------------------------------------------------------------------
#define GBM 128
#define GBN 256
#define GBKT 32
#define ROWB    80
#define APL_B   (128 * ROWB)
#define BPL_B   (256 * ROWB)

template<int NPROD>
__global__ __launch_bounds__(512) void gemm_tc(
    const __half* __restrict__ Ah, const __half* __restrict__ Al,
    const __half* __restrict__ Bh, const __half* __restrict__ Bl,
    float* __restrict__ C, int n0, int N, int K, float cscale)
{
    constexpr int STAGE_B = (NPROD == 3) ? (2 * APL_B + 2 * BPL_B)
                                         : (2 * APL_B + BPL_B);
    constexpr int NSTAGE  = (NPROD == 3) ? 3 : 4;

    extern __shared__ char smg[];
    const uint32_t sb = smem_u32(smg);
    const int tid  = threadIdx.x;
    const int lane = tid & 31;
    const int w    = tid >> 5;
    const int wm   = (w & 3) * 32;
    const int wn   = (w >> 2) * 64;
    const int bn0  = blockIdx.x * GBN + n0;
    const int bm0  = blockIdx.y * GBM;
    const int niter = K / GBKT;

    auto load_stage = [&](int kt, int s) {
        const int NCH = (NPROD == 3) ? 6 : 4;
#pragma unroll
        for (int i = 0; i < NCH; i++) {
            int q = tid + i * 512;
            uint32_t dst;
            const __half* sp;
            if (q < 1024) {
                int pl = q >> 9;
                int r  = q & 511;
                int row = r >> 2, slot = r & 3;
                sp = (pl ? Al : Ah) + (size_t)(bm0 + row) * K
                   + kt * GBKT + slot * 8;
                dst = sb + s * STAGE_B + pl * APL_B + row * ROWB + slot * 16;
            } else {
                int qb = q - 1024;
                int pl = (NPROD == 3) ? (qb >> 10) : 0;
                int r  = qb & 1023;
                int row = r >> 2, slot = r & 3;
                sp = (pl ? Bl : Bh) + (size_t)(bn0 + row) * K
                   + kt * GBKT + slot * 8;
                dst = sb + s * STAGE_B + 2 * APL_B + pl * BPL_B
                    + row * ROWB + slot * 16;
            }
            cpa16(dst, sp);
        }
    };

    float acc[2][8][4];
#pragma unroll
    for (int mt = 0; mt < 2; mt++)
#pragma unroll
        for (int nt = 0; nt < 8; nt++)
#pragma unroll
            for (int e = 0; e < 4; e++) acc[mt][nt][e] = 0.f;

#pragma unroll
    for (int s = 0; s < NSTAGE - 1; s++) {
        load_stage(s, s);
        asm volatile("cp.async.commit_group;");
    }

    const int a_row  = lane & 15, a_half = (lane >> 4) * 8;
    const int b_row2 = (lane & 7) | ((lane >> 1) & 8);
    const int b_half = ((lane >> 3) & 1) * 8;

    int cs = 0, ls = NSTAGE - 1;
    for (int kt = 0; kt < niter; kt++) {
        asm volatile("cp.async.wait_group %0;" :: "n"(NSTAGE - 2));
        __syncthreads();

        if (kt + NSTAGE - 1 < niter)
            load_stage(kt + NSTAGE - 1, ls);
        asm volatile("cp.async.commit_group;");
        if (++ls == NSTAGE) ls = 0;

        const uint32_t sbase = sb + cs * STAGE_B;
        if (++cs == NSTAGE) cs = 0;
#pragma unroll
        for (int ks = 0; ks < GBKT; ks += 16) {
            uint32_t ah[2][4], al[2][4];
#pragma unroll
            for (int mt = 0; mt < 2; mt++) {
                uint32_t aaddr = sbase + (wm + mt * 16 + a_row) * ROWB
                               + (ks + a_half) * 2;
                ldsm_x4(ah[mt], aaddr);
                ldsm_x4(al[mt], aaddr + APL_B);
            }
#pragma unroll
            for (int p = 0; p < 4; p++) {
                uint32_t baddr = sbase + 2 * APL_B
                               + (wn + p * 16 + b_row2) * ROWB
                               + (ks + b_half) * 2;
                uint32_t bh4[4], bl4[4];
                ldsm_x4(bh4, baddr);
                if (NPROD == 3) ldsm_x4(bl4, baddr + BPL_B);
#pragma unroll
                for (int j = 0; j < 2; j++) {
                    int nt = p * 2 + j;
#pragma unroll
                    for (int mt = 0; mt < 2; mt++) {
                        mma_f16(acc[mt][nt], ah[mt], &bh4[2 * j]);
                        if (NPROD == 3)
                            mma_f16(acc[mt][nt], ah[mt], &bl4[2 * j]);
                        mma_f16(acc[mt][nt], al[mt], &bh4[2 * j]);
                    }
                }
            }
        }
        __syncthreads();
    }

    const int cr = lane >> 2, cc = (lane & 3) * 2;
#pragma unroll
    for (int mt = 0; mt < 2; mt++) {
#pragma unroll
        for (int nt = 0; nt < 8; nt++) {
            int row0 = bm0 + wm + mt * 16 + cr;
            int col  = bn0 + wn + nt * 8 + cc;
            *(float2*)&C[(size_t)row0 * N + col] =
                make_float2(acc[mt][nt][0] * cscale, acc[mt][nt][1] * cscale);
            *(float2*)&C[(size_t)(row0 + 8) * N + col] =
                make_float2(acc[mt][nt][2] * cscale, acc[mt][nt][3] * cscale);
        }
    }
}

#define GEMM_SMEM3 (3 * (2 * APL_B + 2 * BPL_B))
#define GEMM_SMEM2 (4 * (2 * APL_B + BPL_B))

// ---------------------------------------------------------------------------
// Prep: RoPE (q,k) / copy (v) from g_qkv -> fp16 hi/lo planes [head][t][d].
// grid (TT/8, 32 slots), block 256 = 8 tokens x 32 lanes, 4 d-pairs per lane.
// NOTE: Q is NOT pre-scaled; SCALE applied inside attention softcap arg.
// ---------------------------------------------------------------------------
__global__ __launch_bounds__(256) void prep_qkv(
    const float* __restrict__ cosb, const float* __restrict__ sinb)
{
    const int hh = blockIdx.y;                 // 0..15 q, 16..23 k, 24..31 v
    const int t  = blockIdx.x * 8 + (threadIdx.x >> 5);
    const int lane = threadIdx.x & 31;
    const int d0 = lane * 4;
    const float* row = g_qkv + (size_t)t * QKVW + hh * HD;

    float x1[4], x2[4], o1[4], o2[4];
    *(float4*)x1 = *(const float4*)(row + d0);
    *(float4*)x2 = *(const float4*)(row + d0 + 128);
    if (hh < NH + NKV) {
        float c[4], s[4];
        *(float4*)c = *(const float4*)(cosb + (size_t)t * 128 + d0);
        *(float4*)s = *(const float4*)(sinb + (size_t)t * 128 + d0);
#pragma unroll
        for (int i = 0; i < 4; i++) {
            o1[i] = x1[i] * c[i] - x2[i] * s[i];
            o2[i] = x2[i] * c[i] + x1[i] * s[i];
        }
    } else {
#pragma unroll
        for (int i = 0; i < 4; i++) { o1[i] = x1[i]; o2[i] = x2[i]; }
    }

    __half *dh, *dl;
    if (hh < NH)           { dh = g_qh + ((size_t)hh * TT + t) * HD;
                             dl = g_ql + ((size_t)hh * TT + t) * HD; }
    else if (hh < NH+NKV)  { dh = g_kh + ((size_t)(hh-NH) * TT + t) * HD;
                             dl = g_kl + ((size_t)(hh-NH) * TT + t) * HD; }
    else                   { dh = g_vh + ((size_t)(hh-NH-NKV) * TT + t) * HD;
                             dl = g_vl + ((size_t)(hh-NH-NKV) * TT + t) * HD; }

#pragma unroll
    for (int i = 0; i < 4; i += 2) {
        __half h0 = __float2half(o1[i]),   h1 = __float2half(o1[i+1]);
        __half g0 = __float2half(o2[i]),   g1 = __float2half(o2[i+1]);
        *(__half2*)(dh + d0 + i)       = __halves2half2(h0, h1);
        *(__half2*)(dh + d0 + 128 + i) = __halves2half2(g0, g1);
        *(__half2*)(dl + d0 + i) = __halves2half2(
            __float2half(o1[i]   - __half2float(h0)),
            __float2half(o1[i+1] - __half2float(h1)));
        *(__half2*)(dl + d0 + 128 + i) = __halves2half2(
            __float2half(o2[i]   - __half2float(g0)),
            __float2half(o2[i+1] - __half2float(g1)));
    }
}

// ---------------------------------------------------------------------------
// Tensor-core flash attention. 256 thr (8 warps), Bq=Bk=64, D=256.
// S: 3-product fp16 split; softmax fp32 in smem; PV: P fp16 x (Vh+Vl).
// Writes aH/aL fp16 hi/lo directly.
// ---------------------------------------------------------------------------
#define DPAD 264                     // halves per Q/K/V tile row
#define STLD 68
#define PTLD 72
#define ATT_SMEM_BYTES (6*64*DPAD*2 + 64*STLD*4 + 64*PTLD*2 + 64*3*4)

__global__ __launch_bounds__(256) void attn_kernel(
    __half* __restrict__ outH, __half* __restrict__ outL)
{
    extern __shared__ __half smh[];
    __half* Qh = smh;
    __half* Ql = Qh + 64 * DPAD;
    __half* Kh = Ql + 64 * DPAD;
    __half* Kl = Kh + 64 * DPAD;
    __half* Vh = Kl + 64 * DPAD;
    __half* Vl = Vh + 64 * DPAD;
    float*  St = (float*)(Vl + 64 * DPAD);
    __half* Pt = (__half*)(St + 64 * STLD);
    float* rowm = (float*)(Pt + 64 * PTLD);
    float* rowl = rowm + 64;
    float* alf  = rowl + 64;

    const int tid  = threadIdx.x;
    const int lane = tid & 31, w = tid >> 5;
    const int qt   = blockIdx.x, h = blockIdx.y, b = blockIdx.z;
    const int qi0  = qt * BQ;
    const int tok0 = b * SEQ;
    const int kh   = h >> 1;

    const uint32_t sQh = smem_u32(Qh), sQl = smem_u32(Ql);
    const uint32_t sKh = smem_u32(Kh), sKl = smem_u32(Kl);
    const uint32_t sVh = smem_u32(Vh), sVl = smem_u32(Vl);
    const uint32_t sPt = smem_u32(Pt);

    const __half* kbaseH = g_kh + ((size_t)kh * TT + tok0) * HD;
    const __half* kbaseL = g_kl + ((size_t)kh * TT + tok0) * HD;
    const __half* vbaseH = g_vh + ((size_t)kh * TT + tok0) * HD;
    const __half* vbaseL = g_vl + ((size_t)kh * TT + tok0) * HD;

    auto load_k = [&](int kj0) {
#pragma unroll
        for (int i = 0; i < 16; i++) {
            int q = tid + i * 256;
            int pl = q >> 11, r = q & 2047;
            int row = r >> 5, slot = r & 31;
            const __half* sp = (pl ? kbaseL : kbaseH)
                             + (size_t)(kj0 + row) * HD + slot * 8;
            cpa16((pl ? sKl : sKh) + row * DPAD * 2 + slot * 16, sp);
        }
        asm volatile("cp.async.commit_group;");
    };
    auto load_v = [&](int kj0) {
#pragma unroll
        for (int i = 0; i < 16; i++) {
            int q = tid + i * 256;
            int pl = q >> 11, r = q & 2047;
            int row = r >> 5, slot = r & 31;
            const __half* sp = (pl ? vbaseL : vbaseH)
                             + (size_t)(kj0 + row) * HD + slot * 8;
            cpa16((pl ? sVl : sVh) + row * DPAD * 2 + slot * 16, sp);
        }
        asm volatile("cp.async.commit_group;");
    };

    // Q load (one-time)
    {
        const __half* qH = g_qh + ((size_t)h * TT + tok0 + qi0) * HD;
        const __half* qL = g_ql + ((size_t)h * TT + tok0 + qi0) * HD;
#pragma unroll
        for (int i = 0; i < 16; i++) {
            int q = tid + i * 256;
            int pl = q >> 11, r = q & 2047;
            int row = r >> 5, slot = r & 31;
            const __half* sp = (pl ? qL : qH) + (size_t)row * HD + slot * 8;
            cpa16((pl ? sQl : sQh) + row * DPAD * 2 + slot * 16, sp);
        }
        asm volatile("cp.async.commit_group;");
    }
    if (tid < 64) { rowm[tid] = -1e30f; rowl[tid] = 0.f; }

    const int wr  = (w & 3) * 16;       // S/O rows
    const int wc  = (w >> 2) * 32;      // S cols
    const int wc2 = (w >> 2) * 128;     // O cols
    const int a_row  = lane & 15, a_half = (lane >> 4) * 8;
    const int b_row2 = (lane & 7) | ((lane >> 1) & 8);
    const int b_half = ((lane >> 3) & 1) * 8;
    const int c_row  = lane >> 2, c_col = (lane & 3) * 2;

    float o[16][4];
#pragma unroll
    for (int nf = 0; nf < 16; nf++)
#pragma unroll
        for (int e = 0; e < 4; e++) o[nf][e] = 0.f;

    const int kt0 = (qi0 - WIN > 0) ? (qi0 - WIN) : 0;
    load_k(kt0);
    load_v(kt0);

    for (int kj0 = kt0; kj0 <= qi0; kj0 += BK) {
        asm volatile("cp.async.wait_group 0;");
        __syncthreads();

        // ---- Phase A: S = Q K^T (3-product) ----
        float s4[4][4];
#pragma unroll
        for (int nf = 0; nf < 4; nf++)
#pragma unroll
            for (int e = 0; e < 4; e++) s4[nf][e] = 0.f;

#pragma unroll
        for (int ks = 0; ks < HD; ks += 16) {
            uint32_t ah[4], al4[4];
            uint32_t aoff = ((wr + a_row) * DPAD + ks + a_half) * 2;
            ldsm_x4(ah,  sQh + aoff);
            ldsm_x4(al4, sQl + aoff);
#pragma unroll
            for (int p = 0; p < 2; p++) {
                uint32_t boff = ((wc + p * 16 + b_row2) * DPAD + ks + b_half) * 2;
                uint32_t kbh[4], kbl[4];
                ldsm_x4(kbh, sKh + boff);
                ldsm_x4(kbl, sKl + boff);
#pragma unroll
                for (int j = 0; j < 2; j++) {
                    int nf = p * 2 + j;
                    mma_f16(s4[nf], ah,  &kbh[2 * j]);
                    mma_f16(s4[nf], ah,  &kbl[2 * j]);
                    mma_f16(s4[nf], al4, &kbh[2 * j]);
                }
            }
        }
        // softcap + mask -> St
        const float cf = SCALE / SOFTCAP;
#pragma unroll
        for (int nf = 0; nf < 4; nf++) {
#pragma unroll
            for (int e = 0; e < 4; e++) {
                int ir = wr + c_row + ((e >> 1) * 8);
                int jc = wc + nf * 8 + c_col + (e & 1);
                float sv = SOFTCAP * tanhf(s4[nf][e] * cf);
                int ig = qi0 + ir, jg = kj0 + jc;
                if (jg > ig || jg < ig - WIN) sv = -1e30f;
                St[ir * STLD + jc] = sv;
            }
        }
        __syncthreads();

        // prefetch next K while softmax+PV run
        if (kj0 + BK <= qi0) load_k(kj0 + BK);

        // ---- Phase B: softmax (64 rows x 4 threads each) ----
        {
            int qr = tid >> 2, sub = tid & 3;
            float mx = -1e30f;
#pragma unroll
            for (int ii = 0; ii < 16; ii++)
                mx = fmaxf(mx, St[qr * STLD + sub * 16 + ii]);
            mx = fmaxf(mx, __shfl_xor_sync(0xffffffffu, mx, 1));
            mx = fmaxf(mx, __shfl_xor_sync(0xffffffffu, mx, 2));
            float mold = rowm[qr];
            float mnew = fmaxf(mold, mx);
            float al   = __expf(mold - mnew);
            float ps   = 0.f;
#pragma unroll
            for (int ii = 0; ii < 16; ii++) {
                float sv = St[qr * STLD + sub * 16 + ii];
                float p  = (sv > -1e29f) ? __expf(sv - mnew) : 0.f;
                __half ph = __float2half(p);
                Pt[qr * PTLD + sub * 16 + ii] = ph;
                ps += __half2float(ph);
            }
            ps += __shfl_xor_sync(0xffffffffu, ps, 1);
            ps += __shfl_xor_sync(0xffffffffu, ps, 2);
            if (sub == 0) {
                rowm[qr] = mnew;
                rowl[qr] = rowl[qr] * al + ps;
                alf[qr]  = al;
            }
        }
        __syncthreads();

        // ---- Phase C: O = diag(alpha) O + P (Vh + Vl) ----
        {
            float a1 = alf[wr + c_row], a2 = alf[wr + c_row + 8];
#pragma unroll
            for (int nf = 0; nf < 16; nf++) {
                o[nf][0] *= a1; o[nf][1] *= a1;
                o[nf][2] *= a2; o[nf][3] *= a2;
            }
#pragma unroll
            for (int kk = 0; kk < BK; kk += 16) {
                uint32_t pf[4];
                ldsm_x4(pf, sPt + ((wr + a_row) * PTLD + kk + a_half) * 2);
#pragma unroll
                for (int dn = 0; dn < 8; dn++) {
                    int d0 = wc2 + dn * 16;
                    uint32_t voff = ((kk + (lane & 15)) * DPAD
                                   + d0 + (lane >> 4) * 8) * 2;
                    uint32_t vbh[4], vbl[4];
                    ldsm_x4t(vbh, sVh + voff);
                    ldsm_x4t(vbl, sVl + voff);
                    mma_f16(o[dn * 2],     pf, &vbh[0]);
                    mma_f16(o[dn * 2],     pf, &vbl[0]);
                    mma_f16(o[dn * 2 + 1], pf, &vbh[2]);
                    mma_f16(o[dn * 2 + 1], pf, &vbl[2]);
                }
            }
        }
        __syncthreads();

        if (kj0 + BK <= qi0) load_v(kj0 + BK);
    }

    // ---- epilogue: normalize, split to fp16 hi/lo, store ----
    {
        int r1 = wr + c_row;
        float i1 = 1.0f / rowl[r1], i2 = 1.0f / rowl[r1 + 8];
        size_t t1 = (size_t)(tok0 + qi0 + r1);
#pragma unroll
        for (int nf = 0; nf < 16; nf++) {
            int col = h * HD + wc2 + nf * 8 + c_col;
            float v0 = o[nf][0] * i1, v1 = o[nf][1] * i1;
            float v2 = o[nf][2] * i2, v3 = o[nf][3] * i2;
            __half h0 = __float2half(v0), h1 = __float2half(v1);
            __half h2 = __float2half(v2), h3 = __float2half(v3);
            *(__half2*)(outH + t1 * ATTW + col) = __halves2half2(h0, h1);
            *(__half2*)(outH + (t1 + 8) * ATTW + col) = __halves2half2(h2, h3);
            *(__half2*)(outL + t1 * ATTW + col) = __halves2half2(
                __float2half(v0 - __half2float(h0)),
                __float2half(v1 - __half2float(h1)));
            *(__half2*)(outL + (t1 + 8) * ATTW + col) = __halves2half2(
                __float2half(v2 - __half2float(h2)),
                __float2half(v3 - __half2float(h3)));
        }
    }
}

// ---------------------------------------------------------------------------
extern "C" void kernel_launch(void* const* d_in, const int* in_sizes, int n_in,
                              void* d_out, int out_size)
{
    const float* hidden = (const float*)d_in[0];
    const float* cosb   = (const float*)d_in[1];
    const float* sinb   = (const float*)d_in[2];
    const float* w_qkv  = (const float*)d_in[3];
    const float* w_o    = (const float*)d_in[4];
    float* out = (float*)d_out;

    float* d_qkv;
    cudaGetSymbolAddress((void**)&d_qkv, g_qkv);
    __half *hH, *hL, *wqH, *wqL, *aH, *aL, *woH, *woL;
    cudaGetSymbolAddress((void**)&hH,  g_hidH);
    cudaGetSymbolAddress((void**)&hL,  g_hidL);
    cudaGetSymbolAddress((void**)&wqH, g_wqH);
    cudaGetSymbolAddress((void**)&wqL, g_wqL);
    cudaGetSymbolAddress((void**)&aH,  g_aH);
    cudaGetSymbolAddress((void**)&aL,  g_aL);
    cudaGetSymbolAddress((void**)&woH, g_woH);
    cudaGetSymbolAddress((void**)&woL, g_woL);

    cudaFuncSetAttribute(gemm_tc<3>, cudaFuncAttributeMaxDynamicSharedMemorySize,
                         GEMM_SMEM3);
    cudaFuncSetAttribute(gemm_tc<2>, cudaFuncAttributeMaxDynamicSharedMemorySize,
                         GEMM_SMEM2);
    cudaFuncSetAttribute(attn_kernel, cudaFuncAttributeMaxDynamicSharedMemorySize,
                         ATT_SMEM_BYTES);

    // 0. split inputs for GEMM1
    {
        size_t n1 = (size_t)TT * HIDDIM;
        size_t n2 = (size_t)QKVW * HIDDIM;
        split_f16<<<(unsigned)((n1 / 4 + 255) / 256), 256>>>(hidden, hH, hL, 1.0f, n1);
        split_f16<<<(unsigned)((n2 / 4 + 255) / 256), 256>>>(w_qkv, wqH, wqL, WSCALE, n2);
    }

    // 1. QKV projection
    gemm_tc<3><<<dim3(6144 / GBN, TT / GBM), 512, GEMM_SMEM3>>>(
        hH, hL, wqH, wqL, d_qkv, 0, QKVW, HIDDIM, CSCALE);
    gemm_tc<2><<<dim3(2048 / GBN, TT / GBM), 512, GEMM_SMEM2>>>(
        hH, hL, wqH, wqL, d_qkv, 6144, QKVW, HIDDIM, CSCALE);

    // 2. RoPE + fp16 hi/lo prep of Q/K/V planes
    prep_qkv<<<dim3(TT / 8, NH + 2 * NKV), 256>>>(cosb, sinb);

    // 3. Tensor-core sliding-window attention (writes aH/aL directly)
    attn_kernel<<<dim3(SEQ / BQ, NH, NB), 256, ATT_SMEM_BYTES>>>(aH, aL);

    // 4. split w_o only (attention already produced aH/aL)
    {
        size_t n4 = (size_t)HIDDIM * ATTW;
        split_f16<<<(unsigned)((n4 / 4 + 255) / 256), 256>>>(w_o, woH, woL, WSCALE, n4);
    }

    // 5. Output projection (2-product)
    gemm_tc<2><<<dim3(HIDDIM / GBN, TT / GBM), 512, GEMM_SMEM2>>>(
        aH, aL, woH, woL, out, 0, HIDDIM, ATTW, CSCALE);
}

// round 15
// speedup vs baseline: 2.6141x; 1.0962x over previous
#include <cuda_runtime.h>
#include <cuda_fp16.h>
#include <math.h>
#include <stdint.h>

#define TT     4096      // total tokens B*S
#define HIDDIM 3584
#define NH     16
#define NKV    8
#define HD     256
#define SEQ    2048
#define NB     2
#define QKVW   8192      // (NH + 2*NKV) * HD
#define ATTW   4096      // NH * HD
#define WIN    1024
#define SCALE  0.0625f   // 256^-0.5
#define SOFTCAP 50.0f

#define BQ 64
#define BK 64

#define WSCALE 32.0f
#define CSCALE (1.0f / 32.0f)

// ---------------- scratch (static device allocations) ----------------------
__device__ float g_qkv[(size_t)TT * QKVW];

// fp16 attention operand planes, layout [head][t][d]
__device__ __half g_qh[(size_t)NH * TT * HD];
__device__ __half g_ql[(size_t)NH * TT * HD];
__device__ __half g_kh[(size_t)NKV * TT * HD];
__device__ __half g_kl[(size_t)NKV * TT * HD];
__device__ __half g_vh[(size_t)NKV * TT * HD];

// fp16 split planes for projections
__device__ __half g_hidH[(size_t)TT * HIDDIM];
__device__ __half g_hidL[(size_t)TT * HIDDIM];
__device__ __half g_wqH[(size_t)QKVW * HIDDIM];
__device__ __half g_wqL[(size_t)QKVW * HIDDIM];
__device__ __half g_aH[(size_t)TT * ATTW];
__device__ __half g_aL[(size_t)TT * ATTW];
__device__ __half g_woH[(size_t)HIDDIM * ATTW];
__device__ __half g_woL[(size_t)HIDDIM * ATTW];

// ---------------------------------------------------------------------------
// fp32 -> fp16 hi/lo split (with pre-scale)
// ---------------------------------------------------------------------------
__global__ __launch_bounds__(256) void split_f16(
    const float* __restrict__ src,
    __half* __restrict__ hi, __half* __restrict__ lo, float scale, size_t n)
{
    size_t i = ((size_t)blockIdx.x * blockDim.x + threadIdx.x) * 4;
    if (i >= n) return;
    float4 v = *(const float4*)(src + i);
    v.x *= scale; v.y *= scale; v.z *= scale; v.w *= scale;
    __half h0 = __float2half(v.x), h1 = __float2half(v.y);
    __half h2 = __float2half(v.z), h3 = __float2half(v.w);
    __half l0 = __float2half(v.x - __half2float(h0));
    __half l1 = __float2half(v.y - __half2float(h1));
    __half l2 = __float2half(v.z - __half2float(h2));
    __half l3 = __float2half(v.w - __half2float(h3));
    *(__half2*)(hi + i)     = __halves2half2(h0, h1);
    *(__half2*)(hi + i + 2) = __halves2half2(h2, h3);
    *(__half2*)(lo + i)     = __halves2half2(l0, l1);
    *(__half2*)(lo + i + 2) = __halves2half2(l2, l3);
}

// ---------------------------------------------------------------------------
// helpers
// ---------------------------------------------------------------------------
__device__ __forceinline__ uint32_t smem_u32(const void* p) {
    uint32_t a;
    asm("{ .reg .u64 t; cvta.to.shared.u64 t, %1; cvt.u32.u64 %0, t; }"
        : "=r"(a) : "l"(p));
    return a;
}
__device__ __forceinline__ void ldsm_x4(uint32_t* r, uint32_t addr) {
    asm volatile("ldmatrix.sync.aligned.m8n8.x4.shared.b16 {%0,%1,%2,%3}, [%4];"
                 : "=r"(r[0]), "=r"(r[1]), "=r"(r[2]), "=r"(r[3]) : "r"(addr));
}
__device__ __forceinline__ void ldsm_x4t(uint32_t* r, uint32_t addr) {
    asm volatile("ldmatrix.sync.aligned.m8n8.x4.trans.shared.b16 {%0,%1,%2,%3}, [%4];"
                 : "=r"(r[0]), "=r"(r[1]), "=r"(r[2]), "=r"(r[3]) : "r"(addr));
}
__device__ __forceinline__ void mma_f16(float* c, const uint32_t* a,
                                        const uint32_t* b) {
    asm volatile(
        "mma.sync.aligned.m16n8k16.row.col.f32.f16.f16.f32 "
        "{%0,%1,%2,%3}, {%4,%5,%6,%7}, {%8,%9}, {%0,%1,%2,%3};"
        : "+f"(c[0]), "+f"(c[1]), "+f"(c[2]), "+f"(c[3])
        : "r"(a[0]), "r"(a[1]), "r"(a[2]), "r"(a[3]), "r"(b[0]), "r"(b[1]));
}
__device__ __forceinline__ void cpa16(uint32_t dst, const void* src) {
    asm volatile("cp.async.cg.shared.global [%0], [%1], 16;"
                 :: "r"(dst), "l"(src));
}

// ---------------------------------------------------------------------------
// Tensor-core GEMM (NT): BM=128, BN=128, BK=32, 256 threads (8 warps),
// warp tile 32x64. Sized so 2 CTAs co-reside per SM.
// NPROD=3: 2-stage (40KB/stage); NPROD=2: 3-stage (30KB/stage).
// ---------------------------------------------------------------------------
#define GBM 128
#define GBN 128
#define GBKT 32
#define ROWB    80
#define APL_B   (128 * ROWB)          // 10240 : A plane (128 rows)
#define BPL_B   (128 * ROWB)          // 10240 : B plane (128 rows)

template<int NPROD>
__global__ __launch_bounds__(256) void gemm_tc(
    const __half* __restrict__ Ah, const __half* __restrict__ Al,
    const __half* __restrict__ Bh, const __half* __restrict__ Bl,
    float* __restrict__ C, int n0, int N, int K, float cscale)
{
    constexpr int STAGE_B = (NPROD == 3) ? (2 * APL_B + 2 * BPL_B)
                                         : (2 * APL_B + BPL_B);
    constexpr int NSTAGE  = (NPROD == 3) ? 2 : 3;

    extern __shared__ char smg[];
    const uint32_t sb = smem_u32(smg);
    const int tid  = threadIdx.x;
    const int lane = tid & 31;
    const int w    = tid >> 5;           // 0..7
    const int wm   = (w & 3) * 32;
    const int wn   = (w >> 2) * 64;
    const int bn0  = blockIdx.x * GBN + n0;
    const int bm0  = blockIdx.y * GBM;
    const int niter = K / GBKT;

    auto load_stage = [&](int kt, int s) {
        const int NCH = (NPROD == 3) ? 8 : 6;   // 16B chunks / 256 threads
#pragma unroll
        for (int i = 0; i < NCH; i++) {
            int q = tid + i * 256;
            uint32_t dst;
            const __half* sp;
            if (q < 1024) {                    // A planes (hi, lo)
                int pl = q >> 9;
                int r  = q & 511;
                int row = r >> 2, slot = r & 3;
                sp = (pl ? Al : Ah) + (size_t)(bm0 + row) * K
                   + kt * GBKT + slot * 8;
                dst = sb + s * STAGE_B + pl * APL_B + row * ROWB + slot * 16;
            } else {                           // B planes
                int qb = q - 1024;
                int pl = (NPROD == 3) ? (qb >> 9) : 0;
                int r  = qb & 511;
                int row = r >> 2, slot = r & 3;
                sp = (pl ? Bl : Bh) + (size_t)(bn0 + row) * K
                   + kt * GBKT + slot * 8;
                dst = sb + s * STAGE_B + 2 * APL_B + pl * BPL_B
                    + row * ROWB + slot * 16;
            }
            cpa16(dst, sp);
        }
    };

    float acc[2][8][4];
#pragma unroll
    for (int mt = 0; mt < 2; mt++)
#pragma unroll
        for (int nt = 0; nt < 8; nt++)
#pragma unroll
            for (int e = 0; e < 4; e++) acc[mt][nt][e] = 0.f;

#pragma unroll
    for (int s = 0; s < NSTAGE - 1; s++) {
        load_stage(s, s);
        asm volatile("cp.async.commit_group;");
    }

    const int a_row  = lane & 15, a_half = (lane >> 4) * 8;
    const int b_row2 = (lane & 7) | ((lane >> 1) & 8);
    const int b_half = ((lane >> 3) & 1) * 8;

    int cs = 0, ls = NSTAGE - 1;
    for (int kt = 0; kt < niter; kt++) {
        asm volatile("cp.async.wait_group %0;" :: "n"(NSTAGE - 2));
        __syncthreads();

        if (kt + NSTAGE - 1 < niter)
            load_stage(kt + NSTAGE - 1, ls);
        asm volatile("cp.async.commit_group;");
        if (++ls == NSTAGE) ls = 0;

        const uint32_t sbase = sb + cs * STAGE_B;
        if (++cs == NSTAGE) cs = 0;
#pragma unroll
        for (int ks = 0; ks < GBKT; ks += 16) {
            uint32_t ah[2][4], al[2][4];
#pragma unroll
            for (int mt = 0; mt < 2; mt++) {
                uint32_t aaddr = sbase + (wm + mt * 16 + a_row) * ROWB
                               + (ks + a_half) * 2;
                ldsm_x4(ah[mt], aaddr);
                ldsm_x4(al[mt], aaddr + APL_B);
            }
#pragma unroll
            for (int p = 0; p < 4; p++) {
                uint32_t baddr = sbase + 2 * APL_B
                               + (wn + p * 16 + b_row2) * ROWB
                               + (ks + b_half) * 2;
                uint32_t bh4[4], bl4[4];
                ldsm_x4(bh4, baddr);
                if (NPROD == 3) ldsm_x4(bl4, baddr + BPL_B);
#pragma unroll
                for (int j = 0; j < 2; j++) {
                    int nt = p * 2 + j;
#pragma unroll
                    for (int mt = 0; mt < 2; mt++) {
                        mma_f16(acc[mt][nt], ah[mt], &bh4[2 * j]);
                        if (NPROD == 3)
                            mma_f16(acc[mt][nt], ah[mt], &bl4[2 * j]);
                        mma_f16(acc[mt][nt], al[mt], &bh4[2 * j]);
                    }
                }
            }
        }
        __syncthreads();
    }

    const int cr = lane >> 2, cc = (lane & 3) * 2;
#pragma unroll
    for (int mt = 0; mt < 2; mt++) {
#pragma unroll
        for (int nt = 0; nt < 8; nt++) {
            int row0 = bm0 + wm + mt * 16 + cr;
            int col  = bn0 + wn + nt * 8 + cc;
            *(float2*)&C[(size_t)row0 * N + col] =
                make_float2(acc[mt][nt][0] * cscale, acc[mt][nt][1] * cscale);
            *(float2*)&C[(size_t)(row0 + 8) * N + col] =
                make_float2(acc[mt][nt][2] * cscale, acc[mt][nt][3] * cscale);
        }
    }
}

#define GEMM_SMEM3 (2 * (2 * APL_B + 2 * BPL_B))   // 81920
#define GEMM_SMEM2 (3 * (2 * APL_B + BPL_B))       // 92160

// ---------------------------------------------------------------------------
// Prep: RoPE (q,k) / copy (v) from g_qkv -> fp16 planes [head][t][d].
// V gets hi plane only (1-product PV).
// ---------------------------------------------------------------------------
__global__ __launch_bounds__(256) void prep_qkv(
    const float* __restrict__ cosb, const float* __restrict__ sinb)
{
    const int hh = blockIdx.y;                 // 0..15 q, 16..23 k, 24..31 v
    const int t  = blockIdx.x * 8 + (threadIdx.x >> 5);
    const int lane = threadIdx.x & 31;
    const int d0 = lane * 4;
    const float* row = g_qkv + (size_t)t * QKVW + hh * HD;

    float x1[4], x2[4], o1[4], o2[4];
    *(float4*)x1 = *(const float4*)(row + d0);
    *(float4*)x2 = *(const float4*)(row + d0 + 128);
    const bool isv = (hh >= NH + NKV);
    if (!isv) {
        float c[4], s[4];
        *(float4*)c = *(const float4*)(cosb + (size_t)t * 128 + d0);
        *(float4*)s = *(const float4*)(sinb + (size_t)t * 128 + d0);
#pragma unroll
        for (int i = 0; i < 4; i++) {
            o1[i] = x1[i] * c[i] - x2[i] * s[i];
            o2[i] = x2[i] * c[i] + x1[i] * s[i];
        }
    } else {
#pragma unroll
        for (int i = 0; i < 4; i++) { o1[i] = x1[i]; o2[i] = x2[i]; }
    }

    if (isv) {
        __half* dh = g_vh + ((size_t)(hh - NH - NKV) * TT + t) * HD;
#pragma unroll
        for (int i = 0; i < 4; i += 2) {
            *(__half2*)(dh + d0 + i) = __halves2half2(
                __float2half(o1[i]), __float2half(o1[i + 1]));
            *(__half2*)(dh + d0 + 128 + i) = __halves2half2(
                __float2half(o2[i]), __float2half(o2[i + 1]));
        }
        return;
    }

    __half *dh, *dl;
    if (hh < NH) { dh = g_qh + ((size_t)hh * TT + t) * HD;
                   dl = g_ql + ((size_t)hh * TT + t) * HD; }
    else         { dh = g_kh + ((size_t)(hh - NH) * TT + t) * HD;
                   dl = g_kl + ((size_t)(hh - NH) * TT + t) * HD; }

#pragma unroll
    for (int i = 0; i < 4; i += 2) {
        __half h0 = __float2half(o1[i]),   h1 = __float2half(o1[i+1]);
        __half g0 = __float2half(o2[i]),   g1 = __float2half(o2[i+1]);
        *(__half2*)(dh + d0 + i)       = __halves2half2(h0, h1);
        *(__half2*)(dh + d0 + 128 + i) = __halves2half2(g0, g1);
        *(__half2*)(dl + d0 + i) = __halves2half2(
            __float2half(o1[i]   - __half2float(h0)),
            __float2half(o1[i+1] - __half2float(h1)));
        *(__half2*)(dl + d0 + 128 + i) = __halves2half2(
            __float2half(o2[i]   - __half2float(g0)),
            __float2half(o2[i+1] - __half2float(g1)));
    }
}

// ---------------------------------------------------------------------------
// Tensor-core flash attention. 256 thr, Bq=Bk=64, D=256.
// S: 3-product fp16 split; softmax fp32; PV: P fp16 x Vh (1-product).
// ---------------------------------------------------------------------------
#define DPAD 264
#define STLD 68
#define PTLD 72
#define ATT_SMEM_BYTES (5*64*DPAD*2 + 64*STLD*4 + 64*PTLD*2 + 64*3*4)

__global__ __launch_bounds__(256) void attn_kernel(
    __half* __restrict__ outH, __half* __restrict__ outL)
{
    extern __shared__ __half smh[];
    __half* Qh = smh;
    __half* Ql = Qh + 64 * DPAD;
    __half* Kh = Ql + 64 * DPAD;
    __half* Kl = Kh + 64 * DPAD;
    __half* Vh = Kl + 64 * DPAD;
    float*  St = (float*)(Vh + 64 * DPAD);
    __half* Pt = (__half*)(St + 64 * STLD);
    float* rowm = (float*)(Pt + 64 * PTLD);
    float* rowl = rowm + 64;
    float* alf  = rowl + 64;

    const int tid  = threadIdx.x;
    const int lane = tid & 31, w = tid >> 5;
    const int qt   = blockIdx.x, h = blockIdx.y, b = blockIdx.z;
    const int qi0  = qt * BQ;
    const int tok0 = b * SEQ;
    const int kh   = h >> 1;

    const uint32_t sQh = smem_u32(Qh), sQl = smem_u32(Ql);
    const uint32_t sKh = smem_u32(Kh), sKl = smem_u32(Kl);
    const uint32_t sVh = smem_u32(Vh);
    const uint32_t sPt = smem_u32(Pt);

    const __half* kbaseH = g_kh + ((size_t)kh * TT + tok0) * HD;
    const __half* kbaseL = g_kl + ((size_t)kh * TT + tok0) * HD;
    const __half* vbaseH = g_vh + ((size_t)kh * TT + tok0) * HD;

    auto load_k = [&](int kj0) {
#pragma unroll
        for (int i = 0; i < 16; i++) {
            int q = tid + i * 256;
            int pl = q >> 11, r = q & 2047;
            int row = r >> 5, slot = r & 31;
            const __half* sp = (pl ? kbaseL : kbaseH)
                             + (size_t)(kj0 + row) * HD + slot * 8;
            cpa16((pl ? sKl : sKh) + row * DPAD * 2 + slot * 16, sp);
        }
        asm volatile("cp.async.commit_group;");
    };
    auto load_v = [&](int kj0) {
#pragma unroll
        for (int i = 0; i < 8; i++) {
            int q = tid + i * 256;
            int row = q >> 5, slot = q & 31;
            const __half* sp = vbaseH + (size_t)(kj0 + row) * HD + slot * 8;
            cpa16(sVh + row * DPAD * 2 + slot * 16, sp);
        }
        asm volatile("cp.async.commit_group;");
    };

    // Q load (one-time)
    {
        const __half* qH = g_qh + ((size_t)h * TT + tok0 + qi0) * HD;
        const __half* qL = g_ql + ((size_t)h * TT + tok0 + qi0) * HD;
#pragma unroll
        for (int i = 0; i < 16; i++) {
            int q = tid + i * 256;
            int pl = q >> 11, r = q & 2047;
            int row = r >> 5, slot = r & 31;
            const __half* sp = (pl ? qL : qH) + (size_t)row * HD + slot * 8;
            cpa16((pl ? sQl : sQh) + row * DPAD * 2 + slot * 16, sp);
        }
        asm volatile("cp.async.commit_group;");
    }
    if (tid < 64) { rowm[tid] = -1e30f; rowl[tid] = 0.f; }

    const int wr  = (w & 3) * 16;
    const int wc  = (w >> 2) * 32;
    const int wc2 = (w >> 2) * 128;
    const int a_row  = lane & 15, a_half = (lane >> 4) * 8;
    const int b_row2 = (lane & 7) | ((lane >> 1) & 8);
    const int b_half = ((lane >> 3) & 1) * 8;
    const int c_row  = lane >> 2, c_col = (lane & 3) * 2;

    float o[16][4];
#pragma unroll
    for (int nf = 0; nf < 16; nf++)
#pragma unroll
        for (int e = 0; e < 4; e++) o[nf][e] = 0.f;

    const int kt0 = (qi0 - WIN > 0) ? (qi0 - WIN) : 0;
    load_k(kt0);
    load_v(kt0);

    for (int kj0 = kt0; kj0 <= qi0; kj0 += BK) {
        asm volatile("cp.async.wait_group 0;");
        __syncthreads();

        // ---- Phase A: S = Q K^T (3-product) ----
        float s4[4][4];
#pragma unroll
        for (int nf = 0; nf < 4; nf++)
#pragma unroll
            for (int e = 0; e < 4; e++) s4[nf][e] = 0.f;

#pragma unroll
        for (int ks = 0; ks < HD; ks += 16) {
            uint32_t ah[4], al4[4];
            uint32_t aoff = ((wr + a_row) * DPAD + ks + a_half) * 2;
            ldsm_x4(ah,  sQh + aoff);
            ldsm_x4(al4, sQl + aoff);
#pragma unroll
            for (int p = 0; p < 2; p++) {
                uint32_t boff = ((wc + p * 16 + b_row2) * DPAD + ks + b_half) * 2;
                uint32_t kbh[4], kbl[4];
                ldsm_x4(kbh, sKh + boff);
                ldsm_x4(kbl, sKl + boff);
#pragma unroll
                for (int j = 0; j < 2; j++) {
                    int nf = p * 2 + j;
                    mma_f16(s4[nf], ah,  &kbh[2 * j]);
                    mma_f16(s4[nf], ah,  &kbl[2 * j]);
                    mma_f16(s4[nf], al4, &kbh[2 * j]);
                }
            }
        }
        const float cf = SCALE / SOFTCAP;
#pragma unroll
        for (int nf = 0; nf < 4; nf++) {
#pragma unroll
            for (int e = 0; e < 4; e++) {
                int ir = wr + c_row + ((e >> 1) * 8);
                int jc = wc + nf * 8 + c_col + (e & 1);
                float sv = SOFTCAP * tanhf(s4[nf][e] * cf);
                int ig = qi0 + ir, jg = kj0 + jc;
                if (jg > ig || jg < ig - WIN) sv = -1e30f;
                St[ir * STLD + jc] = sv;
            }
        }
        __syncthreads();

        if (kj0 + BK <= qi0) load_k(kj0 + BK);

        // ---- Phase B: softmax ----
        {
            int qr = tid >> 2, sub = tid & 3;
            float mx = -1e30f;
#pragma unroll
            for (int ii = 0; ii < 16; ii++)
                mx = fmaxf(mx, St[qr * STLD + sub * 16 + ii]);
            mx = fmaxf(mx, __shfl_xor_sync(0xffffffffu, mx, 1));
            mx = fmaxf(mx, __shfl_xor_sync(0xffffffffu, mx, 2));
            float mold = rowm[qr];
            float mnew = fmaxf(mold, mx);
            float al   = __expf(mold - mnew);
            float ps   = 0.f;
#pragma unroll
            for (int ii = 0; ii < 16; ii++) {
                float sv = St[qr * STLD + sub * 16 + ii];
                float p  = (sv > -1e29f) ? __expf(sv - mnew) : 0.f;
                __half ph = __float2half(p);
                Pt[qr * PTLD + sub * 16 + ii] = ph;
                ps += __half2float(ph);
            }
            ps += __shfl_xor_sync(0xffffffffu, ps, 1);
            ps += __shfl_xor_sync(0xffffffffu, ps, 2);
            if (sub == 0) {
                rowm[qr] = mnew;
                rowl[qr] = rowl[qr] * al + ps;
                alf[qr]  = al;
            }
        }
        __syncthreads();

        // ---- Phase C: O = diag(alpha) O + P Vh ----
        {
            float a1 = alf[wr + c_row], a2 = alf[wr + c_row + 8];
#pragma unroll
            for (int nf = 0; nf < 16; nf++) {
                o[nf][0] *= a1; o[nf][1] *= a1;
                o[nf][2] *= a2; o[nf][3] *= a2;
            }
#pragma unroll
            for (int kk = 0; kk < BK; kk += 16) {
                uint32_t pf[4];
                ldsm_x4(pf, sPt + ((wr + a_row) * PTLD + kk + a_half) * 2);
#pragma unroll
                for (int dn = 0; dn < 8; dn++) {
                    int d0 = wc2 + dn * 16;
                    uint32_t voff = ((kk + (lane & 15)) * DPAD
                                   + d0 + (lane >> 4) * 8) * 2;
                    uint32_t vbh[4];
                    ldsm_x4t(vbh, sVh + voff);
                    mma_f16(o[dn * 2],     pf, &vbh[0]);
                    mma_f16(o[dn * 2 + 1], pf, &vbh[2]);
                }
            }
        }
        __syncthreads();

        if (kj0 + BK <= qi0) load_v(kj0 + BK);
    }

    // ---- epilogue: normalize, split to fp16 hi/lo, store ----
    {
        int r1 = wr + c_row;
        float i1 = 1.0f / rowl[r1], i2 = 1.0f / rowl[r1 + 8];
        size_t t1 = (size_t)(tok0 + qi0 + r1);
#pragma unroll
        for (int nf = 0; nf < 16; nf++) {
            int col = h * HD + wc2 + nf * 8 + c_col;
            float v0 = o[nf][0] * i1, v1 = o[nf][1] * i1;
            float v2 = o[nf][2] * i2, v3 = o[nf][3] * i2;
            __half h0 = __float2half(v0), h1 = __float2half(v1);
            __half h2 = __float2half(v2), h3 = __float2half(v3);
            *(__half2*)(outH + t1 * ATTW + col) = __halves2half2(h0, h1);
            *(__half2*)(outH + (t1 + 8) * ATTW + col) = __halves2half2(h2, h3);
            *(__half2*)(outL + t1 * ATTW + col) = __halves2half2(
                __float2half(v0 - __half2float(h0)),
                __float2half(v1 - __half2float(h1)));
            *(__half2*)(outL + (t1 + 8) * ATTW + col) = __halves2half2(
                __float2half(v2 - __half2float(h2)),
                __float2half(v3 - __half2float(h3)));
        }
    }
}

// ---------------------------------------------------------------------------
extern "C" void kernel_launch(void* const* d_in, const int* in_sizes, int n_in,
                              void* d_out, int out_size)
{
    const float* hidden = (const float*)d_in[0];
    const float* cosb   = (const float*)d_in[1];
    const float* sinb   = (const float*)d_in[2];
    const float* w_qkv  = (const float*)d_in[3];
    const float* w_o    = (const float*)d_in[4];
    float* out = (float*)d_out;

    float* d_qkv;
    cudaGetSymbolAddress((void**)&d_qkv, g_qkv);
    __half *hH, *hL, *wqH, *wqL, *aH, *aL, *woH, *woL;
    cudaGetSymbolAddress((void**)&hH,  g_hidH);
    cudaGetSymbolAddress((void**)&hL,  g_hidL);
    cudaGetSymbolAddress((void**)&wqH, g_wqH);
    cudaGetSymbolAddress((void**)&wqL, g_wqL);
    cudaGetSymbolAddress((void**)&aH,  g_aH);
    cudaGetSymbolAddress((void**)&aL,  g_aL);
    cudaGetSymbolAddress((void**)&woH, g_woH);
    cudaGetSymbolAddress((void**)&woL, g_woL);

    cudaFuncSetAttribute(gemm_tc<3>, cudaFuncAttributeMaxDynamicSharedMemorySize,
                         GEMM_SMEM3);
    cudaFuncSetAttribute(gemm_tc<2>, cudaFuncAttributeMaxDynamicSharedMemorySize,
                         GEMM_SMEM2);
    cudaFuncSetAttribute(attn_kernel, cudaFuncAttributeMaxDynamicSharedMemorySize,
                         ATT_SMEM_BYTES);

    // 0. split inputs for GEMM1
    {
        size_t n1 = (size_t)TT * HIDDIM;
        size_t n2 = (size_t)QKVW * HIDDIM;
        split_f16<<<(unsigned)((n1 / 4 + 255) / 256), 256>>>(hidden, hH, hL, 1.0f, n1);
        split_f16<<<(unsigned)((n2 / 4 + 255) / 256), 256>>>(w_qkv, wqH, wqL, WSCALE, n2);
    }

    // 1. QKV projection: Q+K columns (3-product), V columns (2-product)
    gemm_tc<3><<<dim3(6144 / GBN, TT / GBM), 256, GEMM_SMEM3>>>(
        hH, hL, wqH, wqL, d_qkv, 0, QKVW, HIDDIM, CSCALE);
    gemm_tc<2><<<dim3(2048 / GBN, TT / GBM), 256, GEMM_SMEM2>>>(
        hH, hL, wqH, wqL, d_qkv, 6144, QKVW, HIDDIM, CSCALE);

    // 2. RoPE + fp16 prep of Q/K (hi/lo) and V (hi) planes
    prep_qkv<<<dim3(TT / 8, NH + 2 * NKV), 256>>>(cosb, sinb);

    // 3. Tensor-core sliding-window attention (writes aH/aL directly)
    attn_kernel<<<dim3(SEQ / BQ, NH, NB), 256, ATT_SMEM_BYTES>>>(aH, aL);

    // 4. split w_o only
    {
        size_t n4 = (size_t)HIDDIM * ATTW;
        split_f16<<<(unsigned)((n4 / 4 + 255) / 256), 256>>>(w_o, woH, woL, WSCALE, n4);
    }

    // 5. Output projection (2-product)
    gemm_tc<2><<<dim3(HIDDIM / GBN, TT / GBM), 256, GEMM_SMEM2>>>(
        aH, aL, woH, woL, out, 0, HIDDIM, ATTW, CSCALE);
}